// round 7
// baseline (speedup 1.0000x reference)
#include <cuda_runtime.h>
#include <math.h>
#include <stdint.h>

#define BB 2
#define CC 128
#define HH 256      // 2*C
#define SS 4096     // 64*64 tokens
#define NH 4
#define DD 32       // head dim

#define QS 0.1767766952966369f   // 1/sqrt(32)
#define QS2 (QS * 1.4426950408889634f)   // fold log2(e) for ex2-domain softmax

// ---------------- scratch (no allocation allowed) ----------------
__device__ float g_qp[BB*SS*CC];
__device__ float g_kp[BB*SS*CC];
__device__ float g_vp[BB*SS*CC];
__device__ float g_x [BB*SS*CC];
__device__ float g_r1[BB*SS*CC];

__device__ __forceinline__ const float* sel_in(int sel, const float* ext) {
    switch (sel) {
        case 0: return g_qp; case 1: return g_kp; case 2: return g_vp;
        case 3: return g_x;  case 4: return g_r1;
    }
    return ext;
}
__device__ __forceinline__ float* sel_out(int sel, float* ext) {
    switch (sel) {
        case 0: return g_qp; case 1: return g_kp; case 2: return g_vp;
        case 3: return g_x;  case 4: return g_r1;
    }
    return ext;
}

// tf32 mma m16n8k8 row.col: D += A*B
__device__ __forceinline__ void mma_tf32(float* c, const uint32_t* a, uint32_t b0, uint32_t b1) {
    asm volatile(
        "mma.sync.aligned.m16n8k8.row.col.f32.tf32.tf32.f32 "
        "{%0,%1,%2,%3}, {%4,%5,%6,%7}, {%8,%9}, {%0,%1,%2,%3};"
        : "+f"(c[0]), "+f"(c[1]), "+f"(c[2]), "+f"(c[3])
        : "r"(a[0]), "r"(a[1]), "r"(a[2]), "r"(a[3]), "r"(b0), "r"(b1));
}
__device__ __forceinline__ float tf32rna(float x) {
    uint32_t r;
    asm("cvt.rna.tf32.f32 %0, %1;" : "=r"(r) : "f"(x));
    return __uint_as_float(r);
}
__device__ __forceinline__ uint32_t fbits(float x) { return __float_as_uint(x); }
__device__ __forceinline__ float fexp2(float x) {
    float r;
    asm("ex2.approx.f32 %0, %1;" : "=f"(r) : "f"(x));
    return r;
}

// ================= projection smem layout =================
#define XSTR 132
#define HCSTR 68
#define W1STR 72
#define W2STR 136   // 136 mod 32 = 8 -> conflict-free stage-2 B reads
#define PROJ_SMEM_FLOATS (64*XSTR + 64*HCSTR + 9216 + 256 + 128 + 128 + 128 + 64 + 64)
#define PROJ_SMEM_BYTES (PROJ_SMEM_FLOATS*4)

struct ProjSet { const float *gam, *bet, *w1, *b1, *w2, *b2; };
struct QKVArgs { const float* in[3]; ProjSet ps[3]; };

// ---- 256-thread body (qkv projections: CHW input + LN) ----
__device__ __forceinline__ void proj_body256(
    const float* __restrict__ in, const float* __restrict__ gamma, const float* __restrict__ beta,
    const float* __restrict__ w1, const float* __restrict__ b1,
    const float* __restrict__ w2, const float* __restrict__ b2,
    float* __restrict__ out, int bx)
{
    extern __shared__ float sm[];
    float* Xs  = sm;                    // [64][132]
    float* Hcs = Xs + 64*XSTR;          // [64][68]
    float* Ws  = Hcs + 64*HCSTR;        // [128][72] / [64][136]
    float* Bs1 = Ws + 9216;             // [256]
    float* Bs2 = Bs1 + 256;             // [128]
    float* Gs  = Bs2 + 128;             // [128]
    float* Bts = Gs + 128;              // [128]
    float* MUs = Bts + 128;             // [64]
    float* RIs = MUs + 64;              // [64]

    const int tid  = threadIdx.x;
    const int wid  = tid >> 5;
    const int lane = tid & 31;
    const int g    = lane >> 2;
    const int t    = lane & 3;
    const int mrow  = (wid & 3) * 16;
    const int nhalf = (wid >> 2) * 32;

    const int gt0 = bx * 64;
    const int b   = gt0 >> 12;
    const int s0  = gt0 & (SS - 1);

    if (tid < 256) Bs1[tid] = b1[tid];
    if (tid < 128) { Bs2[tid] = b2[tid]; Gs[tid] = gamma[tid]; Bts[tid] = beta[tid]; }

    {
        const float* base = in + (size_t)b*CC*SS + s0;
        for (int i = tid; i < 64*CC; i += 256) {
            int c = i >> 6, tt = i & 63;
            Xs[tt*XSTR + c] = base[c*SS + tt];
        }
    }
    __syncthreads();

    if (tid < 64) {
        float s = 0.f, s2 = 0.f;
        const float* xr = &Xs[tid*XSTR];
        for (int c = 0; c < CC; c++) { float v = xr[c]; s += v; s2 += v*v; }
        float mu = s * (1.0f/CC);
        float var = s2 * (1.0f/CC) - mu*mu;
        MUs[tid] = mu;
        RIs[tid] = rsqrtf(var + 1e-5f);
    }
    __syncthreads();
    for (int i = tid; i < 64*CC; i += 256) {
        int tt = i >> 7, c = i & 127;
        float v = Xs[tt*XSTR + c];
        v = (v - MUs[tt]) * RIs[tt] * Gs[c] + Bts[c];
        Xs[tt*XSTR + c] = tf32rna(v);
    }
    __syncthreads();

    float acc2[2][4][4];
    #pragma unroll
    for (int n2 = 0; n2 < 2; n2++)
        #pragma unroll
        for (int jn = 0; jn < 4; jn++)
            acc2[n2][jn][0] = acc2[n2][jn][1] = acc2[n2][jn][2] = acc2[n2][jn][3] = 0.f;

    for (int hc = 0; hc < 4; hc++) {
        for (int i = tid; i < 128*16; i += 256) {
            int kk = i >> 4, j4 = i & 15;
            float4 wv = *reinterpret_cast<const float4*>(w1 + kk*HH + hc*64 + j4*4);
            float* d = &Ws[kk*W1STR + j4*4];
            d[0] = tf32rna(wv.x); d[1] = tf32rna(wv.y);
            d[2] = tf32rna(wv.z); d[3] = tf32rna(wv.w);
        }
        __syncthreads();

        float acc[4][4];
        #pragma unroll
        for (int jn = 0; jn < 4; jn++)
            acc[jn][0] = acc[jn][1] = acc[jn][2] = acc[jn][3] = 0.f;
        #pragma unroll
        for (int ks = 0; ks < 16; ks++) {
            uint32_t a[4];
            const float* x0 = &Xs[(mrow+g)*XSTR + ks*8];
            const float* x1 = x0 + 8*XSTR;
            a[0] = fbits(x0[t]); a[1] = fbits(x1[t]);
            a[2] = fbits(x0[t+4]); a[3] = fbits(x1[t+4]);
            #pragma unroll
            for (int jn = 0; jn < 4; jn++) {
                const float* wr = &Ws[(ks*8+t)*W1STR + nhalf + jn*8 + g];
                mma_tf32(acc[jn], a, fbits(wr[0]), fbits(wr[4*W1STR]));
            }
        }
        #pragma unroll
        for (int jn = 0; jn < 4; jn++) {
            int col = nhalf + jn*8 + 2*t;
            float c0 = acc[jn][0] + Bs1[hc*64 + col];
            float c1 = acc[jn][1] + Bs1[hc*64 + col + 1];
            float c2 = acc[jn][2] + Bs1[hc*64 + col];
            float c3 = acc[jn][3] + Bs1[hc*64 + col + 1];
            c0 = (c0 > 0.f) ? c0 : 0.01f*c0;
            c1 = (c1 > 0.f) ? c1 : 0.01f*c1;
            c2 = (c2 > 0.f) ? c2 : 0.01f*c2;
            c3 = (c3 > 0.f) ? c3 : 0.01f*c3;
            float* h0 = &Hcs[(mrow+g)*HCSTR + col];
            float* h1 = &Hcs[(mrow+g+8)*HCSTR + col];
            h0[0] = tf32rna(c0); h0[1] = tf32rna(c1);
            h1[0] = tf32rna(c2); h1[1] = tf32rna(c3);
        }
        __syncthreads();

        for (int i = tid; i < 64*32; i += 256) {
            int kk = i >> 5, j4 = i & 31;
            float4 wv = *reinterpret_cast<const float4*>(w2 + (size_t)(hc*64+kk)*CC + j4*4);
            float* d = &Ws[kk*W2STR + j4*4];
            d[0] = tf32rna(wv.x); d[1] = tf32rna(wv.y);
            d[2] = tf32rna(wv.z); d[3] = tf32rna(wv.w);
        }
        __syncthreads();

        #pragma unroll
        for (int ks = 0; ks < 8; ks++) {
            uint32_t a[4];
            const float* h0 = &Hcs[(mrow+g)*HCSTR + ks*8];
            const float* h1 = h0 + 8*HCSTR;
            a[0] = fbits(h0[t]); a[1] = fbits(h1[t]);
            a[2] = fbits(h0[t+4]); a[3] = fbits(h1[t+4]);
            #pragma unroll
            for (int n2 = 0; n2 < 2; n2++) {
                #pragma unroll
                for (int jn = 0; jn < 4; jn++) {
                    const float* wr = &Ws[(ks*8+t)*W2STR + n2*64 + nhalf + jn*8 + g];
                    mma_tf32(acc2[n2][jn], a, fbits(wr[0]), fbits(wr[4*W2STR]));
                }
            }
        }
        __syncthreads();
    }

    #pragma unroll
    for (int n2 = 0; n2 < 2; n2++) {
        #pragma unroll
        for (int jn = 0; jn < 4; jn++) {
            int col = n2*64 + nhalf + jn*8 + 2*t;
            float* y0 = &Xs[(mrow+g)*XSTR + col];
            float* y1 = &Xs[(mrow+g+8)*XSTR + col];
            y0[0] = acc2[n2][jn][0] + Bs2[col];
            y0[1] = acc2[n2][jn][1] + Bs2[col+1];
            y1[0] = acc2[n2][jn][2] + Bs2[col];
            y1[1] = acc2[n2][jn][3] + Bs2[col+1];
        }
    }
    __syncthreads();

    float* ob = out + (size_t)gt0*CC;
    for (int i = tid; i < 64*CC; i += 256) {
        int tt = i >> 7, c = i & 127;
        ob[i] = Xs[tt*XSTR + c];
    }
}

// fused q/k/v projections: grid 384, group = blockIdx.x / 128
__global__ __launch_bounds__(256, 2)
void qkv_proj_kernel(QKVArgs a)
{
    const int grp = blockIdx.x >> 7;
    const int bx  = blockIdx.x & 127;
    float* outp = (grp == 0) ? g_qp : (grp == 1) ? g_kp : g_vp;
    const ProjSet& p = a.ps[grp];
    proj_body256(a.in[grp], p.gam, p.bet, p.w1, p.b1, p.w2, p.b2, outp, bx);
}

// ---- 512-thread MLP body: 4 m-groups x 4 n-groups, 64 tokens, residual ----
template<bool OUT_CHW>
__global__ __launch_bounds__(512, 1)
void mlp_tc_kernel(int in_sel, const float* __restrict__ w1, const float* __restrict__ b1,
                   const float* __restrict__ w2, const float* __restrict__ b2,
                   int res_sel, float* __restrict__ out_ext, int out_sel)
{
    extern __shared__ float sm[];
    float* Xs  = sm;                    // [64][132]
    float* Hcs = Xs + 64*XSTR;          // [64][68]
    float* Ws  = Hcs + 64*HCSTR;        // [128][72] / [64][136]
    float* Bs1 = Ws + 9216;             // [256]
    float* Bs2 = Bs1 + 256;             // [128]

    const float* in  = sel_in(in_sel, nullptr);
    const float* res = sel_in(res_sel, nullptr);
    float*       out = sel_out(out_sel, out_ext);

    const int tid  = threadIdx.x;
    const int wid  = tid >> 5;
    const int lane = tid & 31;
    const int g    = lane >> 2;
    const int t    = lane & 3;
    const int mrow = (wid & 3) * 16;
    const int ngrp = wid >> 2;          // 0..3

    const int gt0 = blockIdx.x * 64;
    const int b   = gt0 >> 12;
    const int s0  = gt0 & (SS - 1);

    if (tid < 256) Bs1[tid] = b1[tid];
    else if (tid < 384) Bs2[tid - 256] = b2[tid - 256];

    {
        const float* base = in + (size_t)gt0*CC;
        for (int i = tid; i < 64*CC; i += 512) {
            int tt = i >> 7, c = i & 127;
            Xs[tt*XSTR + c] = tf32rna(base[i]);
        }
    }
    __syncthreads();

    float acc2[4][4];   // this warp's 32 output cols (4 n8 frags)
    #pragma unroll
    for (int jn = 0; jn < 4; jn++)
        acc2[jn][0] = acc2[jn][1] = acc2[jn][2] = acc2[jn][3] = 0.f;

    for (int hc = 0; hc < 4; hc++) {
        // W1 chunk [128 k][64 n]
        for (int i = tid; i < 128*16; i += 512) {
            int kk = i >> 4, j4 = i & 15;
            float4 wv = *reinterpret_cast<const float4*>(w1 + kk*HH + hc*64 + j4*4);
            float* d = &Ws[kk*W1STR + j4*4];
            d[0] = tf32rna(wv.x); d[1] = tf32rna(wv.y);
            d[2] = tf32rna(wv.z); d[3] = tf32rna(wv.w);
        }
        __syncthreads();

        // stage1: this warp covers 16 cols (2 jn frags)
        float acc[2][4];
        #pragma unroll
        for (int jn = 0; jn < 2; jn++)
            acc[jn][0] = acc[jn][1] = acc[jn][2] = acc[jn][3] = 0.f;
        #pragma unroll
        for (int ks = 0; ks < 16; ks++) {
            uint32_t a[4];
            const float* x0 = &Xs[(mrow+g)*XSTR + ks*8];
            const float* x1 = x0 + 8*XSTR;
            a[0] = fbits(x0[t]); a[1] = fbits(x1[t]);
            a[2] = fbits(x0[t+4]); a[3] = fbits(x1[t+4]);
            #pragma unroll
            for (int jn = 0; jn < 2; jn++) {
                const float* wr = &Ws[(ks*8+t)*W1STR + ngrp*16 + jn*8 + g];
                mma_tf32(acc[jn], a, fbits(wr[0]), fbits(wr[4*W1STR]));
            }
        }
        #pragma unroll
        for (int jn = 0; jn < 2; jn++) {
            int col = ngrp*16 + jn*8 + 2*t;
            float c0 = acc[jn][0] + Bs1[hc*64 + col];
            float c1 = acc[jn][1] + Bs1[hc*64 + col + 1];
            float c2 = acc[jn][2] + Bs1[hc*64 + col];
            float c3 = acc[jn][3] + Bs1[hc*64 + col + 1];
            c0 = (c0 > 0.f) ? c0 : 0.01f*c0;
            c1 = (c1 > 0.f) ? c1 : 0.01f*c1;
            c2 = (c2 > 0.f) ? c2 : 0.01f*c2;
            c3 = (c3 > 0.f) ? c3 : 0.01f*c3;
            float* h0 = &Hcs[(mrow+g)*HCSTR + col];
            float* h1 = &Hcs[(mrow+g+8)*HCSTR + col];
            h0[0] = tf32rna(c0); h0[1] = tf32rna(c1);
            h1[0] = tf32rna(c2); h1[1] = tf32rna(c3);
        }
        __syncthreads();

        // W2 chunk [64 k][128 n]
        for (int i = tid; i < 64*32; i += 512) {
            int kk = i >> 5, j4 = i & 31;
            float4 wv = *reinterpret_cast<const float4*>(w2 + (size_t)(hc*64+kk)*CC + j4*4);
            float* d = &Ws[kk*W2STR + j4*4];
            d[0] = tf32rna(wv.x); d[1] = tf32rna(wv.y);
            d[2] = tf32rna(wv.z); d[3] = tf32rna(wv.w);
        }
        __syncthreads();

        // stage2 partial: this warp's 32 cols
        #pragma unroll
        for (int ks = 0; ks < 8; ks++) {
            uint32_t a[4];
            const float* h0 = &Hcs[(mrow+g)*HCSTR + ks*8];
            const float* h1 = h0 + 8*HCSTR;
            a[0] = fbits(h0[t]); a[1] = fbits(h1[t]);
            a[2] = fbits(h0[t+4]); a[3] = fbits(h1[t+4]);
            #pragma unroll
            for (int jn = 0; jn < 4; jn++) {
                const float* wr = &Ws[(ks*8+t)*W2STR + ngrp*32 + jn*8 + g];
                mma_tf32(acc2[jn], a, fbits(wr[0]), fbits(wr[4*W2STR]));
            }
        }
        __syncthreads();
    }

    // Y + bias into Xs
    #pragma unroll
    for (int jn = 0; jn < 4; jn++) {
        int col = ngrp*32 + jn*8 + 2*t;
        float* y0 = &Xs[(mrow+g)*XSTR + col];
        float* y1 = &Xs[(mrow+g+8)*XSTR + col];
        y0[0] = acc2[jn][0] + Bs2[col];
        y0[1] = acc2[jn][1] + Bs2[col+1];
        y1[0] = acc2[jn][2] + Bs2[col];
        y1[1] = acc2[jn][3] + Bs2[col+1];
    }
    __syncthreads();

    // residual (token-major, coalesced)
    {
        const float* rb = res + (size_t)gt0*CC;
        for (int i = tid; i < 64*CC; i += 512) {
            int tt = i >> 7, c = i & 127;
            Xs[tt*XSTR + c] += rb[i];
        }
    }
    __syncthreads();

    if (OUT_CHW) {
        float* ob = out + (size_t)b*CC*SS + s0;
        for (int i = tid; i < 64*CC; i += 512) {
            int c = i >> 6, tt = i & 63;
            ob[c*SS + tt] = Xs[tt*XSTR + c];
        }
    } else {
        float* ob = out + (size_t)gt0*CC;
        for (int i = tid; i < 64*CC; i += 512) {
            int tt = i >> 7, c = i & 127;
            ob[i] = Xs[tt*XSTR + c];
        }
    }
}

// ================= mma.sync tf32 flash attention (unchanged, known-good) =================
#define KVSTRIDE 36

__global__ __launch_bounds__(128, 2) void attn_mma_kernel()
{
    __shared__ __align__(16) float Ks[2][64*KVSTRIDE];
    __shared__ __align__(16) float Vs[2][64*KVSTRIDE];

    const int tid  = threadIdx.x;
    const int wid  = tid >> 5;
    const int lane = tid & 31;
    const int g    = lane >> 2;
    const int t    = lane & 3;
    const int h = blockIdx.y, b = blockIdx.z;
    const int q0 = blockIdx.x * 128;

    const float* qg = g_qp + ((size_t)b*SS)*CC + h*DD;
    const float* kg = g_kp + ((size_t)b*SS)*CC + h*DD;
    const float* vg = g_vp + ((size_t)b*SS)*CC + h*DD;

    uint32_t qa[2][4][4];
    #pragma unroll
    for (int mf = 0; mf < 2; mf++) {
        const int r0 = q0 + wid*32 + mf*16 + g;
        const float* qrow0 = qg + (size_t)r0*CC;
        const float* qrow1 = qrow0 + 8*CC;
        #pragma unroll
        for (int kt = 0; kt < 4; kt++) {
            qa[mf][kt][0] = fbits(qrow0[kt*8 + t]     * QS2);
            qa[mf][kt][1] = fbits(qrow1[kt*8 + t]     * QS2);
            qa[mf][kt][2] = fbits(qrow0[kt*8 + t + 4] * QS2);
            qa[mf][kt][3] = fbits(qrow1[kt*8 + t + 4] * QS2);
        }
    }

    float O[2][4][4];
    float m[2][2], l[2][2];
    #pragma unroll
    for (int mf = 0; mf < 2; mf++) {
        #pragma unroll
        for (int j = 0; j < 4; j++)
            #pragma unroll
            for (int i = 0; i < 4; i++) O[mf][j][i] = 0.f;
        m[mf][0] = m[mf][1] = -1e30f;
        l[mf][0] = l[mf][1] = 0.f;
    }

    const int srcA = (lane & ~3) | (t >> 1);
    const int srcB = srcA + 2;

    auto cp_tile = [&](int tile, int buf) {
        #pragma unroll
        for (int r = 0; r < 4; r++) {
            int idx = tid + r*128;
            int row = idx >> 3, c4 = idx & 7;
            size_t goff = (size_t)(tile*64 + row)*CC + c4*4;
            uint32_t kd = (uint32_t)__cvta_generic_to_shared(&Ks[buf][row*KVSTRIDE + c4*4]);
            uint32_t vd = (uint32_t)__cvta_generic_to_shared(&Vs[buf][row*KVSTRIDE + c4*4]);
            asm volatile("cp.async.ca.shared.global [%0], [%1], 16;" :: "r"(kd), "l"(kg + goff));
            asm volatile("cp.async.ca.shared.global [%0], [%1], 16;" :: "r"(vd), "l"(vg + goff));
        }
        asm volatile("cp.async.commit_group;" ::: "memory");
    };

    cp_tile(0, 0);

    for (int tile = 0; tile < SS/64; tile++) {
        const int buf = tile & 1;
        if (tile + 1 < SS/64) {
            cp_tile(tile + 1, buf ^ 1);
            asm volatile("cp.async.wait_group 1;" ::: "memory");
        } else {
            asm volatile("cp.async.wait_group 0;" ::: "memory");
        }
        __syncthreads();

        float s[2][8][4];
        #pragma unroll
        for (int jn = 0; jn < 8; jn++) {
            #pragma unroll
            for (int mf = 0; mf < 2; mf++)
                s[mf][jn][0] = s[mf][jn][1] = s[mf][jn][2] = s[mf][jn][3] = 0.f;
            const float* krow = &Ks[buf][(jn*8 + g)*KVSTRIDE];
            #pragma unroll
            for (int kt = 0; kt < 4; kt++) {
                uint32_t b0 = fbits(krow[kt*8 + t]);
                uint32_t b1 = fbits(krow[kt*8 + t + 4]);
                mma_tf32(s[0][jn], qa[0][kt], b0, b1);
                mma_tf32(s[1][jn], qa[1][kt], b0, b1);
            }
        }

        float corr[2][2];
        #pragma unroll
        for (int mf = 0; mf < 2; mf++) {
            float mt0 = s[mf][0][0], mt1 = s[mf][0][2];
            #pragma unroll
            for (int jn = 0; jn < 8; jn++) {
                mt0 = fmaxf(mt0, fmaxf(s[mf][jn][0], s[mf][jn][1]));
                mt1 = fmaxf(mt1, fmaxf(s[mf][jn][2], s[mf][jn][3]));
            }
            mt0 = fmaxf(mt0, __shfl_xor_sync(0xffffffffu, mt0, 1));
            mt0 = fmaxf(mt0, __shfl_xor_sync(0xffffffffu, mt0, 2));
            mt1 = fmaxf(mt1, __shfl_xor_sync(0xffffffffu, mt1, 1));
            mt1 = fmaxf(mt1, __shfl_xor_sync(0xffffffffu, mt1, 2));
            const float mn0 = fmaxf(m[mf][0], mt0), mn1 = fmaxf(m[mf][1], mt1);
            corr[mf][0] = fexp2(m[mf][0] - mn0);
            corr[mf][1] = fexp2(m[mf][1] - mn1);
            m[mf][0] = mn0; m[mf][1] = mn1;
            float ls0 = 0.f, ls1 = 0.f;
            #pragma unroll
            for (int jn = 0; jn < 8; jn++) {
                s[mf][jn][0] = fexp2(s[mf][jn][0] - mn0); ls0 += s[mf][jn][0];
                s[mf][jn][1] = fexp2(s[mf][jn][1] - mn0); ls0 += s[mf][jn][1];
                s[mf][jn][2] = fexp2(s[mf][jn][2] - mn1); ls1 += s[mf][jn][2];
                s[mf][jn][3] = fexp2(s[mf][jn][3] - mn1); ls1 += s[mf][jn][3];
            }
            l[mf][0] = l[mf][0]*corr[mf][0] + ls0;
            l[mf][1] = l[mf][1]*corr[mf][1] + ls1;
            #pragma unroll
            for (int j = 0; j < 4; j++) {
                O[mf][j][0] *= corr[mf][0]; O[mf][j][1] *= corr[mf][0];
                O[mf][j][2] *= corr[mf][1]; O[mf][j][3] *= corr[mf][1];
            }
        }

        #pragma unroll
        for (int kk = 0; kk < 8; kk++) {
            uint32_t pa[2][4];
            #pragma unroll
            for (int mf = 0; mf < 2; mf++) {
                float v00 = __shfl_sync(0xffffffffu, s[mf][kk][0], srcA);
                float v01 = __shfl_sync(0xffffffffu, s[mf][kk][1], srcA);
                float v20 = __shfl_sync(0xffffffffu, s[mf][kk][2], srcA);
                float v21 = __shfl_sync(0xffffffffu, s[mf][kk][3], srcA);
                float w00 = __shfl_sync(0xffffffffu, s[mf][kk][0], srcB);
                float w01 = __shfl_sync(0xffffffffu, s[mf][kk][1], srcB);
                float w20 = __shfl_sync(0xffffffffu, s[mf][kk][2], srcB);
                float w21 = __shfl_sync(0xffffffffu, s[mf][kk][3], srcB);
                pa[mf][0] = fbits((t & 1) ? v01 : v00);
                pa[mf][1] = fbits((t & 1) ? v21 : v20);
                pa[mf][2] = fbits((t & 1) ? w01 : w00);
                pa[mf][3] = fbits((t & 1) ? w21 : w20);
            }
            const float* vrow0 = &Vs[buf][(kk*8 + t)*KVSTRIDE];
            const float* vrow1 = &Vs[buf][(kk*8 + t + 4)*KVSTRIDE];
            #pragma unroll
            for (int jn = 0; jn < 4; jn++) {
                uint32_t b0 = fbits(vrow0[jn*8 + g]);
                uint32_t b1 = fbits(vrow1[jn*8 + g]);
                mma_tf32(O[0][jn], pa[0], b0, b1);
                mma_tf32(O[1][jn], pa[1], b0, b1);
            }
        }
        __syncthreads();
    }

    #pragma unroll
    for (int mf = 0; mf < 2; mf++) {
        float l0 = l[mf][0], l1 = l[mf][1];
        l0 += __shfl_xor_sync(0xffffffffu, l0, 1);
        l0 += __shfl_xor_sync(0xffffffffu, l0, 2);
        l1 += __shfl_xor_sync(0xffffffffu, l1, 1);
        l1 += __shfl_xor_sync(0xffffffffu, l1, 2);
        const float inv0 = 1.0f / l0, inv1 = 1.0f / l1;
        const int r0 = q0 + wid*32 + mf*16 + g;
        float* o0 = g_x + ((size_t)b*SS + r0)*CC + h*DD;
        float* o1 = o0 + 8*CC;
        #pragma unroll
        for (int jn = 0; jn < 4; jn++) {
            float2 u0 = make_float2(O[mf][jn][0]*inv0, O[mf][jn][1]*inv0);
            float2 u1 = make_float2(O[mf][jn][2]*inv1, O[mf][jn][3]*inv1);
            *reinterpret_cast<float2*>(o0 + jn*8 + 2*t) = u0;
            *reinterpret_cast<float2*>(o1 + jn*8 + 2*t) = u1;
        }
    }
}

// ---------------- launcher ----------------
extern "C" void kernel_launch(void* const* d_in, const int* in_sizes, int n_in,
                              void* d_out, int out_size)
{
    (void)in_sizes; (void)n_in; (void)out_size;
    const float* q = (const float*)d_in[0];
    const float* k = (const float*)d_in[1];
    const float* v = (const float*)d_in[2];
    float* out = (float*)d_out;

    QKVArgs qa;
    qa.in[0] = q; qa.in[1] = k; qa.in[2] = v;
    qa.ps[0] = ProjSet{ (const float*)d_in[3], (const float*)d_in[4],
                        (const float*)d_in[5], (const float*)d_in[6],
                        (const float*)d_in[7], (const float*)d_in[8] };
    qa.ps[1] = ProjSet{ (const float*)d_in[9], (const float*)d_in[10],
                        (const float*)d_in[11], (const float*)d_in[12],
                        (const float*)d_in[13], (const float*)d_in[14] };
    qa.ps[2] = ProjSet{ (const float*)d_in[15], (const float*)d_in[16],
                        (const float*)d_in[17], (const float*)d_in[18],
                        (const float*)d_in[19], (const float*)d_in[20] };

    const float* m1_w1 = (const float*)d_in[21];
    const float* m1_b1 = (const float*)d_in[22];
    const float* m1_w2 = (const float*)d_in[23];
    const float* m1_b2 = (const float*)d_in[24];
    const float* m2_w1 = (const float*)d_in[25];
    const float* m2_b1 = (const float*)d_in[26];
    const float* m2_w2 = (const float*)d_in[27];
    const float* m2_b2 = (const float*)d_in[28];

    cudaFuncSetAttribute(qkv_proj_kernel,
                         cudaFuncAttributeMaxDynamicSharedMemorySize, PROJ_SMEM_BYTES);
    cudaFuncSetAttribute(mlp_tc_kernel<false>,
                         cudaFuncAttributeMaxDynamicSharedMemorySize, PROJ_SMEM_BYTES);
    cudaFuncSetAttribute(mlp_tc_kernel<true>,
                         cudaFuncAttributeMaxDynamicSharedMemorySize, PROJ_SMEM_BYTES);

    // fused q/k/v projections -> g_qp/g_kp/g_vp
    qkv_proj_kernel<<<384, 256, PROJ_SMEM_BYTES>>>(qa);

    // flash attention -> g_x
    attn_mma_kernel<<<dim3(SS/128, NH, BB), 128>>>();

    // rs1 = vp + mlp1(x) -> g_r1
    mlp_tc_kernel<false><<<128, 512, PROJ_SMEM_BYTES>>>(3, m1_w1, m1_b1, m1_w2, m1_b2, 2, nullptr, 4);

    // rs2 = rs1 + mlp2(rs1) -> out (CHW)
    mlp_tc_kernel<true><<<128, 512, PROJ_SMEM_BYTES>>>(4, m2_w1, m2_b1, m2_w2, m2_b2, 4, out, -1);
}

// round 8
// speedup vs baseline: 1.0687x; 1.0687x over previous
#include <cuda_runtime.h>
#include <math.h>
#include <stdint.h>

#define BB 2
#define CC 128
#define HH 256      // 2*C
#define SS 4096     // 64*64 tokens
#define NH 4
#define DD 32       // head dim

#define QS 0.1767766952966369f   // 1/sqrt(32)
#define QS2 (QS * 1.4426950408889634f)   // fold log2(e) for ex2-domain softmax

// ---------------- scratch (no allocation allowed) ----------------
__device__ float g_qp[BB*SS*CC];
__device__ float g_kp[BB*SS*CC];
__device__ float g_vp[BB*SS*CC];
__device__ float g_x [BB*SS*CC];
__device__ float g_r1[BB*SS*CC];

__device__ __forceinline__ const float* sel_in(int sel, const float* ext) {
    switch (sel) {
        case 0: return g_qp; case 1: return g_kp; case 2: return g_vp;
        case 3: return g_x;  case 4: return g_r1;
    }
    return ext;
}
__device__ __forceinline__ float* sel_out(int sel, float* ext) {
    switch (sel) {
        case 0: return g_qp; case 1: return g_kp; case 2: return g_vp;
        case 3: return g_x;  case 4: return g_r1;
    }
    return ext;
}

// tf32 mma m16n8k8 row.col: D += A*B
__device__ __forceinline__ void mma_tf32(float* c, const uint32_t* a, uint32_t b0, uint32_t b1) {
    asm volatile(
        "mma.sync.aligned.m16n8k8.row.col.f32.tf32.tf32.f32 "
        "{%0,%1,%2,%3}, {%4,%5,%6,%7}, {%8,%9}, {%0,%1,%2,%3};"
        : "+f"(c[0]), "+f"(c[1]), "+f"(c[2]), "+f"(c[3])
        : "r"(a[0]), "r"(a[1]), "r"(a[2]), "r"(a[3]), "r"(b0), "r"(b1));
}
__device__ __forceinline__ float tf32rna(float x) {
    uint32_t r;
    asm("cvt.rna.tf32.f32 %0, %1;" : "=r"(r) : "f"(x));
    return __uint_as_float(r);
}
__device__ __forceinline__ uint32_t fbits(float x) { return __float_as_uint(x); }
__device__ __forceinline__ float fexp2(float x) {
    float r;
    asm("ex2.approx.f32 %0, %1;" : "=f"(r) : "f"(x));
    return r;
}

// ================= projection smem layout =================
#define XSTR 132
#define HCSTR 68
#define W1STR 72
#define W2STR 136   // 136 mod 32 = 8 -> conflict-free stage-2 B reads
// qkv body (single W buffer):
#define PROJ_SMEM_FLOATS (64*XSTR + 64*HCSTR + 9216 + 256 + 128 + 128 + 128 + 64 + 64)
#define PROJ_SMEM_BYTES (PROJ_SMEM_FLOATS*4)
// MLP body (double W buffer, pipelined):
#define MLP_SMEM_FLOATS (64*XSTR + 64*HCSTR + 9216 + 8704 + 256 + 128)
#define MLP_SMEM_BYTES (MLP_SMEM_FLOATS*4)

struct ProjSet { const float *gam, *bet, *w1, *b1, *w2, *b2; };
struct QKVArgs { const float* in[3]; ProjSet ps[3]; };

// ---- 256-thread body (qkv projections: CHW input + LN) — round-6 known-good ----
__device__ __forceinline__ void proj_body256(
    const float* __restrict__ in, const float* __restrict__ gamma, const float* __restrict__ beta,
    const float* __restrict__ w1, const float* __restrict__ b1,
    const float* __restrict__ w2, const float* __restrict__ b2,
    float* __restrict__ out, int bx)
{
    extern __shared__ float sm[];
    float* Xs  = sm;                    // [64][132]
    float* Hcs = Xs + 64*XSTR;          // [64][68]
    float* Ws  = Hcs + 64*HCSTR;        // [128][72] / [64][136]
    float* Bs1 = Ws + 9216;             // [256]
    float* Bs2 = Bs1 + 256;             // [128]
    float* Gs  = Bs2 + 128;             // [128]
    float* Bts = Gs + 128;              // [128]
    float* MUs = Bts + 128;             // [64]
    float* RIs = MUs + 64;              // [64]

    const int tid  = threadIdx.x;
    const int wid  = tid >> 5;
    const int lane = tid & 31;
    const int g    = lane >> 2;
    const int t    = lane & 3;
    const int mrow  = (wid & 3) * 16;
    const int nhalf = (wid >> 2) * 32;

    const int gt0 = bx * 64;
    const int b   = gt0 >> 12;
    const int s0  = gt0 & (SS - 1);

    if (tid < 256) Bs1[tid] = b1[tid];
    if (tid < 128) { Bs2[tid] = b2[tid]; Gs[tid] = gamma[tid]; Bts[tid] = beta[tid]; }

    {
        const float* base = in + (size_t)b*CC*SS + s0;
        for (int i = tid; i < 64*CC; i += 256) {
            int c = i >> 6, tt = i & 63;
            Xs[tt*XSTR + c] = base[c*SS + tt];
        }
    }
    __syncthreads();

    if (tid < 64) {
        float s = 0.f, s2 = 0.f;
        const float* xr = &Xs[tid*XSTR];
        for (int c = 0; c < CC; c++) { float v = xr[c]; s += v; s2 += v*v; }
        float mu = s * (1.0f/CC);
        float var = s2 * (1.0f/CC) - mu*mu;
        MUs[tid] = mu;
        RIs[tid] = rsqrtf(var + 1e-5f);
    }
    __syncthreads();
    for (int i = tid; i < 64*CC; i += 256) {
        int tt = i >> 7, c = i & 127;
        float v = Xs[tt*XSTR + c];
        v = (v - MUs[tt]) * RIs[tt] * Gs[c] + Bts[c];
        Xs[tt*XSTR + c] = tf32rna(v);
    }
    __syncthreads();

    float acc2[2][4][4];
    #pragma unroll
    for (int n2 = 0; n2 < 2; n2++)
        #pragma unroll
        for (int jn = 0; jn < 4; jn++)
            acc2[n2][jn][0] = acc2[n2][jn][1] = acc2[n2][jn][2] = acc2[n2][jn][3] = 0.f;

    for (int hc = 0; hc < 4; hc++) {
        for (int i = tid; i < 128*16; i += 256) {
            int kk = i >> 4, j4 = i & 15;
            float4 wv = *reinterpret_cast<const float4*>(w1 + kk*HH + hc*64 + j4*4);
            float* d = &Ws[kk*W1STR + j4*4];
            d[0] = tf32rna(wv.x); d[1] = tf32rna(wv.y);
            d[2] = tf32rna(wv.z); d[3] = tf32rna(wv.w);
        }
        __syncthreads();

        float acc[4][4];
        #pragma unroll
        for (int jn = 0; jn < 4; jn++)
            acc[jn][0] = acc[jn][1] = acc[jn][2] = acc[jn][3] = 0.f;
        #pragma unroll
        for (int ks = 0; ks < 16; ks++) {
            uint32_t a[4];
            const float* x0 = &Xs[(mrow+g)*XSTR + ks*8];
            const float* x1 = x0 + 8*XSTR;
            a[0] = fbits(x0[t]); a[1] = fbits(x1[t]);
            a[2] = fbits(x0[t+4]); a[3] = fbits(x1[t+4]);
            #pragma unroll
            for (int jn = 0; jn < 4; jn++) {
                const float* wr = &Ws[(ks*8+t)*W1STR + nhalf + jn*8 + g];
                mma_tf32(acc[jn], a, fbits(wr[0]), fbits(wr[4*W1STR]));
            }
        }
        #pragma unroll
        for (int jn = 0; jn < 4; jn++) {
            int col = nhalf + jn*8 + 2*t;
            float c0 = acc[jn][0] + Bs1[hc*64 + col];
            float c1 = acc[jn][1] + Bs1[hc*64 + col + 1];
            float c2 = acc[jn][2] + Bs1[hc*64 + col];
            float c3 = acc[jn][3] + Bs1[hc*64 + col + 1];
            c0 = (c0 > 0.f) ? c0 : 0.01f*c0;
            c1 = (c1 > 0.f) ? c1 : 0.01f*c1;
            c2 = (c2 > 0.f) ? c2 : 0.01f*c2;
            c3 = (c3 > 0.f) ? c3 : 0.01f*c3;
            float* h0 = &Hcs[(mrow+g)*HCSTR + col];
            float* h1 = &Hcs[(mrow+g+8)*HCSTR + col];
            h0[0] = tf32rna(c0); h0[1] = tf32rna(c1);
            h1[0] = tf32rna(c2); h1[1] = tf32rna(c3);
        }
        __syncthreads();

        for (int i = tid; i < 64*32; i += 256) {
            int kk = i >> 5, j4 = i & 31;
            float4 wv = *reinterpret_cast<const float4*>(w2 + (size_t)(hc*64+kk)*CC + j4*4);
            float* d = &Ws[kk*W2STR + j4*4];
            d[0] = tf32rna(wv.x); d[1] = tf32rna(wv.y);
            d[2] = tf32rna(wv.z); d[3] = tf32rna(wv.w);
        }
        __syncthreads();

        #pragma unroll
        for (int ks = 0; ks < 8; ks++) {
            uint32_t a[4];
            const float* h0 = &Hcs[(mrow+g)*HCSTR + ks*8];
            const float* h1 = h0 + 8*HCSTR;
            a[0] = fbits(h0[t]); a[1] = fbits(h1[t]);
            a[2] = fbits(h0[t+4]); a[3] = fbits(h1[t+4]);
            #pragma unroll
            for (int n2 = 0; n2 < 2; n2++) {
                #pragma unroll
                for (int jn = 0; jn < 4; jn++) {
                    const float* wr = &Ws[(ks*8+t)*W2STR + n2*64 + nhalf + jn*8 + g];
                    mma_tf32(acc2[n2][jn], a, fbits(wr[0]), fbits(wr[4*W2STR]));
                }
            }
        }
        __syncthreads();
    }

    #pragma unroll
    for (int n2 = 0; n2 < 2; n2++) {
        #pragma unroll
        for (int jn = 0; jn < 4; jn++) {
            int col = n2*64 + nhalf + jn*8 + 2*t;
            float* y0 = &Xs[(mrow+g)*XSTR + col];
            float* y1 = &Xs[(mrow+g+8)*XSTR + col];
            y0[0] = acc2[n2][jn][0] + Bs2[col];
            y0[1] = acc2[n2][jn][1] + Bs2[col+1];
            y1[0] = acc2[n2][jn][2] + Bs2[col];
            y1[1] = acc2[n2][jn][3] + Bs2[col+1];
        }
    }
    __syncthreads();

    float* ob = out + (size_t)gt0*CC;
    for (int i = tid; i < 64*CC; i += 256) {
        int tt = i >> 7, c = i & 127;
        ob[i] = Xs[tt*XSTR + c];
    }
}

// fused q/k/v projections: grid 384, group = blockIdx.x / 128
__global__ __launch_bounds__(256, 2)
void qkv_proj_kernel(QKVArgs a)
{
    const int grp = blockIdx.x >> 7;
    const int bx  = blockIdx.x & 127;
    float* outp = (grp == 0) ? g_qp : (grp == 1) ? g_kp : g_vp;
    const ProjSet& p = a.ps[grp];
    proj_body256(a.in[grp], p.gam, p.bet, p.w1, p.b1, p.w2, p.b2, outp, bx);
}

// ---- pipelined 256-thread MLP: register-prefetched weights, split W buffers ----
template<bool OUT_CHW>
__global__ __launch_bounds__(256, 1)
void mlp_tc_kernel(int in_sel, const float* __restrict__ w1, const float* __restrict__ b1,
                   const float* __restrict__ w2, const float* __restrict__ b2,
                   int res_sel, float* __restrict__ out_ext, int out_sel)
{
    extern __shared__ float sm[];
    float* Xs  = sm;                    // [64][132]
    float* Hcs = Xs + 64*XSTR;          // [64][68]
    float* WsA = Hcs + 64*HCSTR;        // [128][72]  W1 chunk
    float* WsB = WsA + 9216;            // [64][136]  W2 chunk
    float* Bs1 = WsB + 8704;            // [256]
    float* Bs2 = Bs1 + 256;             // [128]

    const float* in  = sel_in(in_sel, nullptr);
    const float* res = sel_in(res_sel, nullptr);
    float*       out = sel_out(out_sel, out_ext);

    const int tid  = threadIdx.x;
    const int wid  = tid >> 5;
    const int lane = tid & 31;
    const int g    = lane >> 2;
    const int t    = lane & 3;
    const int mrow  = (wid & 3) * 16;
    const int nhalf = (wid >> 2) * 32;

    const int gt0 = blockIdx.x * 64;
    const int b   = gt0 >> 12;
    const int s0  = gt0 & (SS - 1);

    if (tid < 256) Bs1[tid] = b1[tid];
    if (tid < 128) Bs2[tid] = b2[tid];

    float4 wreg[8];
    // prefetch W1 chunk 0
    #pragma unroll
    for (int j = 0; j < 8; j++) {
        int idx = tid + j*256;
        int kk = idx >> 4, j4 = idx & 15;
        wreg[j] = *reinterpret_cast<const float4*>(w1 + kk*HH + 0*64 + j4*4);
    }

    {
        const float* base = in + (size_t)gt0*CC;
        for (int i = tid; i < 64*CC; i += 256) {
            int tt = i >> 7, c = i & 127;
            Xs[tt*XSTR + c] = tf32rna(base[i]);
        }
    }

    float acc2[2][4][4];
    #pragma unroll
    for (int n2 = 0; n2 < 2; n2++)
        #pragma unroll
        for (int jn = 0; jn < 4; jn++)
            acc2[n2][jn][0] = acc2[n2][jn][1] = acc2[n2][jn][2] = acc2[n2][jn][3] = 0.f;

    for (int hc = 0; hc < 4; hc++) {
        // store W1 regs -> WsA (rna), then prefetch W2 chunk hc
        #pragma unroll
        for (int j = 0; j < 8; j++) {
            int idx = tid + j*256;
            int kk = idx >> 4, j4 = idx & 15;
            float* d = &WsA[kk*W1STR + j4*4];
            d[0] = tf32rna(wreg[j].x); d[1] = tf32rna(wreg[j].y);
            d[2] = tf32rna(wreg[j].z); d[3] = tf32rna(wreg[j].w);
        }
        #pragma unroll
        for (int j = 0; j < 8; j++) {
            int idx = tid + j*256;
            int kk = idx >> 5, j4 = idx & 31;
            wreg[j] = *reinterpret_cast<const float4*>(w2 + (size_t)(hc*64+kk)*CC + j4*4);
        }
        __syncthreads();   // WsA visible (and Xs on hc==0)

        // stage 1: Hc = leaky(X @ W1c + b1c)
        float acc[4][4];
        #pragma unroll
        for (int jn = 0; jn < 4; jn++)
            acc[jn][0] = acc[jn][1] = acc[jn][2] = acc[jn][3] = 0.f;
        #pragma unroll
        for (int ks = 0; ks < 16; ks++) {
            uint32_t a[4];
            const float* x0 = &Xs[(mrow+g)*XSTR + ks*8];
            const float* x1 = x0 + 8*XSTR;
            a[0] = fbits(x0[t]); a[1] = fbits(x1[t]);
            a[2] = fbits(x0[t+4]); a[3] = fbits(x1[t+4]);
            #pragma unroll
            for (int jn = 0; jn < 4; jn++) {
                const float* wr = &WsA[(ks*8+t)*W1STR + nhalf + jn*8 + g];
                mma_tf32(acc[jn], a, fbits(wr[0]), fbits(wr[4*W1STR]));
            }
        }
        #pragma unroll
        for (int jn = 0; jn < 4; jn++) {
            int col = nhalf + jn*8 + 2*t;
            float c0 = acc[jn][0] + Bs1[hc*64 + col];
            float c1 = acc[jn][1] + Bs1[hc*64 + col + 1];
            float c2 = acc[jn][2] + Bs1[hc*64 + col];
            float c3 = acc[jn][3] + Bs1[hc*64 + col + 1];
            c0 = (c0 > 0.f) ? c0 : 0.01f*c0;
            c1 = (c1 > 0.f) ? c1 : 0.01f*c1;
            c2 = (c2 > 0.f) ? c2 : 0.01f*c2;
            c3 = (c3 > 0.f) ? c3 : 0.01f*c3;
            float* h0 = &Hcs[(mrow+g)*HCSTR + col];
            float* h1 = &Hcs[(mrow+g+8)*HCSTR + col];
            h0[0] = tf32rna(c0); h0[1] = tf32rna(c1);
            h1[0] = tf32rna(c2); h1[1] = tf32rna(c3);
        }
        __syncthreads();   // Hcs visible, WsA free

        // store W2 regs -> WsB (rna), then prefetch W1 chunk hc+1
        #pragma unroll
        for (int j = 0; j < 8; j++) {
            int idx = tid + j*256;
            int kk = idx >> 5, j4 = idx & 31;
            float* d = &WsB[kk*W2STR + j4*4];
            d[0] = tf32rna(wreg[j].x); d[1] = tf32rna(wreg[j].y);
            d[2] = tf32rna(wreg[j].z); d[3] = tf32rna(wreg[j].w);
        }
        if (hc < 3) {
            #pragma unroll
            for (int j = 0; j < 8; j++) {
                int idx = tid + j*256;
                int kk = idx >> 4, j4 = idx & 15;
                wreg[j] = *reinterpret_cast<const float4*>(w1 + kk*HH + (hc+1)*64 + j4*4);
            }
        }
        __syncthreads();   // WsB visible

        // stage 2 partial: acc2 += Hc @ W2c
        #pragma unroll
        for (int ks = 0; ks < 8; ks++) {
            uint32_t a[4];
            const float* h0 = &Hcs[(mrow+g)*HCSTR + ks*8];
            const float* h1 = h0 + 8*HCSTR;
            a[0] = fbits(h0[t]); a[1] = fbits(h1[t]);
            a[2] = fbits(h0[t+4]); a[3] = fbits(h1[t+4]);
            #pragma unroll
            for (int n2 = 0; n2 < 2; n2++) {
                #pragma unroll
                for (int jn = 0; jn < 4; jn++) {
                    const float* wr = &WsB[(ks*8+t)*W2STR + n2*64 + nhalf + jn*8 + g];
                    mma_tf32(acc2[n2][jn], a, fbits(wr[0]), fbits(wr[4*W2STR]));
                }
            }
        }
        __syncthreads();   // Hcs free for next stage1 write; WsB free
    }

    // Y + bias into Xs
    #pragma unroll
    for (int n2 = 0; n2 < 2; n2++) {
        #pragma unroll
        for (int jn = 0; jn < 4; jn++) {
            int col = n2*64 + nhalf + jn*8 + 2*t;
            float* y0 = &Xs[(mrow+g)*XSTR + col];
            float* y1 = &Xs[(mrow+g+8)*XSTR + col];
            y0[0] = acc2[n2][jn][0] + Bs2[col];
            y0[1] = acc2[n2][jn][1] + Bs2[col+1];
            y1[0] = acc2[n2][jn][2] + Bs2[col];
            y1[1] = acc2[n2][jn][3] + Bs2[col+1];
        }
    }
    __syncthreads();

    // residual
    {
        const float* rb = res + (size_t)gt0*CC;
        for (int i = tid; i < 64*CC; i += 256) {
            int tt = i >> 7, c = i & 127;
            Xs[tt*XSTR + c] += rb[i];
        }
    }
    __syncthreads();

    if (OUT_CHW) {
        float* ob = out + (size_t)b*CC*SS + s0;
        for (int i = tid; i < 64*CC; i += 256) {
            int c = i >> 6, tt = i & 63;
            ob[c*SS + tt] = Xs[tt*XSTR + c];
        }
    } else {
        float* ob = out + (size_t)gt0*CC;
        for (int i = tid; i < 64*CC; i += 256) {
            int tt = i >> 7, c = i & 127;
            ob[i] = Xs[tt*XSTR + c];
        }
    }
}

// ================= mma.sync tf32 flash attention (unchanged, known-good) =================
#define KVSTRIDE 36

__global__ __launch_bounds__(128, 2) void attn_mma_kernel()
{
    __shared__ __align__(16) float Ks[2][64*KVSTRIDE];
    __shared__ __align__(16) float Vs[2][64*KVSTRIDE];

    const int tid  = threadIdx.x;
    const int wid  = tid >> 5;
    const int lane = tid & 31;
    const int g    = lane >> 2;
    const int t    = lane & 3;
    const int h = blockIdx.y, b = blockIdx.z;
    const int q0 = blockIdx.x * 128;

    const float* qg = g_qp + ((size_t)b*SS)*CC + h*DD;
    const float* kg = g_kp + ((size_t)b*SS)*CC + h*DD;
    const float* vg = g_vp + ((size_t)b*SS)*CC + h*DD;

    uint32_t qa[2][4][4];
    #pragma unroll
    for (int mf = 0; mf < 2; mf++) {
        const int r0 = q0 + wid*32 + mf*16 + g;
        const float* qrow0 = qg + (size_t)r0*CC;
        const float* qrow1 = qrow0 + 8*CC;
        #pragma unroll
        for (int kt = 0; kt < 4; kt++) {
            qa[mf][kt][0] = fbits(qrow0[kt*8 + t]     * QS2);
            qa[mf][kt][1] = fbits(qrow1[kt*8 + t]     * QS2);
            qa[mf][kt][2] = fbits(qrow0[kt*8 + t + 4] * QS2);
            qa[mf][kt][3] = fbits(qrow1[kt*8 + t + 4] * QS2);
        }
    }

    float O[2][4][4];
    float m[2][2], l[2][2];
    #pragma unroll
    for (int mf = 0; mf < 2; mf++) {
        #pragma unroll
        for (int j = 0; j < 4; j++)
            #pragma unroll
            for (int i = 0; i < 4; i++) O[mf][j][i] = 0.f;
        m[mf][0] = m[mf][1] = -1e30f;
        l[mf][0] = l[mf][1] = 0.f;
    }

    const int srcA = (lane & ~3) | (t >> 1);
    const int srcB = srcA + 2;

    auto cp_tile = [&](int tile, int buf) {
        #pragma unroll
        for (int r = 0; r < 4; r++) {
            int idx = tid + r*128;
            int row = idx >> 3, c4 = idx & 7;
            size_t goff = (size_t)(tile*64 + row)*CC + c4*4;
            uint32_t kd = (uint32_t)__cvta_generic_to_shared(&Ks[buf][row*KVSTRIDE + c4*4]);
            uint32_t vd = (uint32_t)__cvta_generic_to_shared(&Vs[buf][row*KVSTRIDE + c4*4]);
            asm volatile("cp.async.ca.shared.global [%0], [%1], 16;" :: "r"(kd), "l"(kg + goff));
            asm volatile("cp.async.ca.shared.global [%0], [%1], 16;" :: "r"(vd), "l"(vg + goff));
        }
        asm volatile("cp.async.commit_group;" ::: "memory");
    };

    cp_tile(0, 0);

    for (int tile = 0; tile < SS/64; tile++) {
        const int buf = tile & 1;
        if (tile + 1 < SS/64) {
            cp_tile(tile + 1, buf ^ 1);
            asm volatile("cp.async.wait_group 1;" ::: "memory");
        } else {
            asm volatile("cp.async.wait_group 0;" ::: "memory");
        }
        __syncthreads();

        float s[2][8][4];
        #pragma unroll
        for (int jn = 0; jn < 8; jn++) {
            #pragma unroll
            for (int mf = 0; mf < 2; mf++)
                s[mf][jn][0] = s[mf][jn][1] = s[mf][jn][2] = s[mf][jn][3] = 0.f;
            const float* krow = &Ks[buf][(jn*8 + g)*KVSTRIDE];
            #pragma unroll
            for (int kt = 0; kt < 4; kt++) {
                uint32_t b0 = fbits(krow[kt*8 + t]);
                uint32_t b1 = fbits(krow[kt*8 + t + 4]);
                mma_tf32(s[0][jn], qa[0][kt], b0, b1);
                mma_tf32(s[1][jn], qa[1][kt], b0, b1);
            }
        }

        float corr[2][2];
        #pragma unroll
        for (int mf = 0; mf < 2; mf++) {
            float mt0 = s[mf][0][0], mt1 = s[mf][0][2];
            #pragma unroll
            for (int jn = 0; jn < 8; jn++) {
                mt0 = fmaxf(mt0, fmaxf(s[mf][jn][0], s[mf][jn][1]));
                mt1 = fmaxf(mt1, fmaxf(s[mf][jn][2], s[mf][jn][3]));
            }
            mt0 = fmaxf(mt0, __shfl_xor_sync(0xffffffffu, mt0, 1));
            mt0 = fmaxf(mt0, __shfl_xor_sync(0xffffffffu, mt0, 2));
            mt1 = fmaxf(mt1, __shfl_xor_sync(0xffffffffu, mt1, 1));
            mt1 = fmaxf(mt1, __shfl_xor_sync(0xffffffffu, mt1, 2));
            const float mn0 = fmaxf(m[mf][0], mt0), mn1 = fmaxf(m[mf][1], mt1);
            corr[mf][0] = fexp2(m[mf][0] - mn0);
            corr[mf][1] = fexp2(m[mf][1] - mn1);
            m[mf][0] = mn0; m[mf][1] = mn1;
            float ls0 = 0.f, ls1 = 0.f;
            #pragma unroll
            for (int jn = 0; jn < 8; jn++) {
                s[mf][jn][0] = fexp2(s[mf][jn][0] - mn0); ls0 += s[mf][jn][0];
                s[mf][jn][1] = fexp2(s[mf][jn][1] - mn0); ls0 += s[mf][jn][1];
                s[mf][jn][2] = fexp2(s[mf][jn][2] - mn1); ls1 += s[mf][jn][2];
                s[mf][jn][3] = fexp2(s[mf][jn][3] - mn1); ls1 += s[mf][jn][3];
            }
            l[mf][0] = l[mf][0]*corr[mf][0] + ls0;
            l[mf][1] = l[mf][1]*corr[mf][1] + ls1;
            #pragma unroll
            for (int j = 0; j < 4; j++) {
                O[mf][j][0] *= corr[mf][0]; O[mf][j][1] *= corr[mf][0];
                O[mf][j][2] *= corr[mf][1]; O[mf][j][3] *= corr[mf][1];
            }
        }

        #pragma unroll
        for (int kk = 0; kk < 8; kk++) {
            uint32_t pa[2][4];
            #pragma unroll
            for (int mf = 0; mf < 2; mf++) {
                float v00 = __shfl_sync(0xffffffffu, s[mf][kk][0], srcA);
                float v01 = __shfl_sync(0xffffffffu, s[mf][kk][1], srcA);
                float v20 = __shfl_sync(0xffffffffu, s[mf][kk][2], srcA);
                float v21 = __shfl_sync(0xffffffffu, s[mf][kk][3], srcA);
                float w00 = __shfl_sync(0xffffffffu, s[mf][kk][0], srcB);
                float w01 = __shfl_sync(0xffffffffu, s[mf][kk][1], srcB);
                float w20 = __shfl_sync(0xffffffffu, s[mf][kk][2], srcB);
                float w21 = __shfl_sync(0xffffffffu, s[mf][kk][3], srcB);
                pa[mf][0] = fbits((t & 1) ? v01 : v00);
                pa[mf][1] = fbits((t & 1) ? v21 : v20);
                pa[mf][2] = fbits((t & 1) ? w01 : w00);
                pa[mf][3] = fbits((t & 1) ? w21 : w20);
            }
            const float* vrow0 = &Vs[buf][(kk*8 + t)*KVSTRIDE];
            const float* vrow1 = &Vs[buf][(kk*8 + t + 4)*KVSTRIDE];
            #pragma unroll
            for (int jn = 0; jn < 4; jn++) {
                uint32_t b0 = fbits(vrow0[jn*8 + g]);
                uint32_t b1 = fbits(vrow1[jn*8 + g]);
                mma_tf32(O[0][jn], pa[0], b0, b1);
                mma_tf32(O[1][jn], pa[1], b0, b1);
            }
        }
        __syncthreads();
    }

    #pragma unroll
    for (int mf = 0; mf < 2; mf++) {
        float l0 = l[mf][0], l1 = l[mf][1];
        l0 += __shfl_xor_sync(0xffffffffu, l0, 1);
        l0 += __shfl_xor_sync(0xffffffffu, l0, 2);
        l1 += __shfl_xor_sync(0xffffffffu, l1, 1);
        l1 += __shfl_xor_sync(0xffffffffu, l1, 2);
        const float inv0 = 1.0f / l0, inv1 = 1.0f / l1;
        const int r0 = q0 + wid*32 + mf*16 + g;
        float* o0 = g_x + ((size_t)b*SS + r0)*CC + h*DD;
        float* o1 = o0 + 8*CC;
        #pragma unroll
        for (int jn = 0; jn < 4; jn++) {
            float2 u0 = make_float2(O[mf][jn][0]*inv0, O[mf][jn][1]*inv0);
            float2 u1 = make_float2(O[mf][jn][2]*inv1, O[mf][jn][3]*inv1);
            *reinterpret_cast<float2*>(o0 + jn*8 + 2*t) = u0;
            *reinterpret_cast<float2*>(o1 + jn*8 + 2*t) = u1;
        }
    }
}

// ---------------- launcher ----------------
extern "C" void kernel_launch(void* const* d_in, const int* in_sizes, int n_in,
                              void* d_out, int out_size)
{
    (void)in_sizes; (void)n_in; (void)out_size;
    const float* q = (const float*)d_in[0];
    const float* k = (const float*)d_in[1];
    const float* v = (const float*)d_in[2];
    float* out = (float*)d_out;

    QKVArgs qa;
    qa.in[0] = q; qa.in[1] = k; qa.in[2] = v;
    qa.ps[0] = ProjSet{ (const float*)d_in[3], (const float*)d_in[4],
                        (const float*)d_in[5], (const float*)d_in[6],
                        (const float*)d_in[7], (const float*)d_in[8] };
    qa.ps[1] = ProjSet{ (const float*)d_in[9], (const float*)d_in[10],
                        (const float*)d_in[11], (const float*)d_in[12],
                        (const float*)d_in[13], (const float*)d_in[14] };
    qa.ps[2] = ProjSet{ (const float*)d_in[15], (const float*)d_in[16],
                        (const float*)d_in[17], (const float*)d_in[18],
                        (const float*)d_in[19], (const float*)d_in[20] };

    const float* m1_w1 = (const float*)d_in[21];
    const float* m1_b1 = (const float*)d_in[22];
    const float* m1_w2 = (const float*)d_in[23];
    const float* m1_b2 = (const float*)d_in[24];
    const float* m2_w1 = (const float*)d_in[25];
    const float* m2_b1 = (const float*)d_in[26];
    const float* m2_w2 = (const float*)d_in[27];
    const float* m2_b2 = (const float*)d_in[28];

    cudaFuncSetAttribute(qkv_proj_kernel,
                         cudaFuncAttributeMaxDynamicSharedMemorySize, PROJ_SMEM_BYTES);
    cudaFuncSetAttribute(mlp_tc_kernel<false>,
                         cudaFuncAttributeMaxDynamicSharedMemorySize, MLP_SMEM_BYTES);
    cudaFuncSetAttribute(mlp_tc_kernel<true>,
                         cudaFuncAttributeMaxDynamicSharedMemorySize, MLP_SMEM_BYTES);

    // fused q/k/v projections -> g_qp/g_kp/g_vp
    qkv_proj_kernel<<<384, 256, PROJ_SMEM_BYTES>>>(qa);

    // flash attention -> g_x
    attn_mma_kernel<<<dim3(SS/128, NH, BB), 128>>>();

    // rs1 = vp + mlp1(x) -> g_r1
    mlp_tc_kernel<false><<<128, 256, MLP_SMEM_BYTES>>>(3, m1_w1, m1_b1, m1_w2, m1_b2, 2, nullptr, 4);

    // rs2 = rs1 + mlp2(rs1) -> out (CHW)
    mlp_tc_kernel<true><<<128, 256, MLP_SMEM_BYTES>>>(4, m2_w1, m2_b1, m2_w2, m2_b2, 4, out, -1);
}

// round 9
// speedup vs baseline: 1.4654x; 1.3712x over previous
#include <cuda_runtime.h>
#include <math.h>
#include <stdint.h>

#define BB 2
#define CC 128
#define HH 256      // 2*C
#define SS 4096     // 64*64 tokens
#define NH 4
#define DD 32       // head dim

#define QS 0.1767766952966369f   // 1/sqrt(32)
#define QS2 (QS * 1.4426950408889634f)   // fold log2(e) for ex2-domain softmax

// ---------------- scratch (no allocation allowed) ----------------
__device__ uint32_t g_qph[BB*SS*CC/2];   // fp16 Q, token-major, pre-scaled by QS*log2e
__device__ uint32_t g_kph[BB*SS*CC/2];   // fp16 K, token-major
__device__ uint32_t g_vph[BB*SS*CC/2];   // fp16 V, d-major: [b][h][d][s]
__device__ float g_vp[BB*SS*CC];         // fp32 V (residual for mlp1)
__device__ float g_x [BB*SS*CC];
__device__ float g_r1[BB*SS*CC];

__device__ __forceinline__ const float* sel_in(int sel) {
    switch (sel) { case 2: return g_vp; case 3: return g_x; case 4: return g_r1; }
    return g_x;
}
__device__ __forceinline__ float* sel_out(int sel, float* ext) {
    switch (sel) { case 2: return g_vp; case 3: return g_x; case 4: return g_r1; }
    return ext;
}

// tf32 mma m16n8k8 row.col
__device__ __forceinline__ void mma_tf32(float* c, const uint32_t* a, uint32_t b0, uint32_t b1) {
    asm volatile(
        "mma.sync.aligned.m16n8k8.row.col.f32.tf32.tf32.f32 "
        "{%0,%1,%2,%3}, {%4,%5,%6,%7}, {%8,%9}, {%0,%1,%2,%3};"
        : "+f"(c[0]), "+f"(c[1]), "+f"(c[2]), "+f"(c[3])
        : "r"(a[0]), "r"(a[1]), "r"(a[2]), "r"(a[3]), "r"(b0), "r"(b1));
}
// fp16 mma m16n8k16 row.col, fp32 accumulate
__device__ __forceinline__ void mma_f16(float* c, const uint32_t* a, uint32_t b0, uint32_t b1) {
    asm volatile(
        "mma.sync.aligned.m16n8k16.row.col.f32.f16.f16.f32 "
        "{%0,%1,%2,%3}, {%4,%5,%6,%7}, {%8,%9}, {%0,%1,%2,%3};"
        : "+f"(c[0]), "+f"(c[1]), "+f"(c[2]), "+f"(c[3])
        : "r"(a[0]), "r"(a[1]), "r"(a[2]), "r"(a[3]), "r"(b0), "r"(b1));
}
__device__ __forceinline__ float tf32rna(float x) {
    uint32_t r;
    asm("cvt.rna.tf32.f32 %0, %1;" : "=r"(r) : "f"(x));
    return __uint_as_float(r);
}
__device__ __forceinline__ uint32_t fbits(float x) { return __float_as_uint(x); }
__device__ __forceinline__ float fexp2(float x) {
    float r;
    asm("ex2.approx.f32 %0, %1;" : "=f"(r) : "f"(x));
    return r;
}
// pack {hi, lo} floats -> f16x2 (lo in low half)
__device__ __forceinline__ uint32_t cvt2h(float hi, float lo) {
    uint32_t r;
    asm("cvt.rn.f16x2.f32 %0, %1, %2;" : "=r"(r) : "f"(hi), "f"(lo));
    return r;
}

// ================= projection smem layout =================
#define XSTR 132
#define HCSTR 68
#define W1STR 72
#define W2STR 136
#define PROJ_SMEM_FLOATS (64*XSTR + 64*HCSTR + 9216 + 256 + 128 + 128 + 128 + 64 + 64)
#define PROJ_SMEM_BYTES (PROJ_SMEM_FLOATS*4)
#define MLP_SMEM_FLOATS (64*XSTR + 64*HCSTR + 9216 + 8704 + 256 + 128)
#define MLP_SMEM_BYTES (MLP_SMEM_FLOATS*4)

struct ProjSet { const float *gam, *bet, *w1, *b1, *w2, *b2; };
struct QKVArgs { const float* in[3]; ProjSet ps[3]; };

// ---- 256-thread qkv body: CHW input + LN, grp-specific fp16 outputs ----
__device__ __forceinline__ void proj_body256(
    const float* __restrict__ in, const float* __restrict__ gamma, const float* __restrict__ beta,
    const float* __restrict__ w1, const float* __restrict__ b1,
    const float* __restrict__ w2, const float* __restrict__ b2,
    int grp, int bx)
{
    extern __shared__ float sm[];
    float* Xs  = sm;
    float* Hcs = Xs + 64*XSTR;
    float* Ws  = Hcs + 64*HCSTR;
    float* Bs1 = Ws + 9216;
    float* Bs2 = Bs1 + 256;
    float* Gs  = Bs2 + 128;
    float* Bts = Gs + 128;
    float* MUs = Bts + 128;
    float* RIs = MUs + 64;

    const int tid  = threadIdx.x;
    const int wid  = tid >> 5;
    const int lane = tid & 31;
    const int g    = lane >> 2;
    const int t    = lane & 3;
    const int mrow  = (wid & 3) * 16;
    const int nhalf = (wid >> 2) * 32;

    const int gt0 = bx * 64;
    const int b   = gt0 >> 12;
    const int s0  = gt0 & (SS - 1);

    if (tid < 256) Bs1[tid] = b1[tid];
    if (tid < 128) { Bs2[tid] = b2[tid]; Gs[tid] = gamma[tid]; Bts[tid] = beta[tid]; }

    {
        const float* base = in + (size_t)b*CC*SS + s0;
        for (int i = tid; i < 64*CC; i += 256) {
            int c = i >> 6, tt = i & 63;
            Xs[tt*XSTR + c] = base[c*SS + tt];
        }
    }
    __syncthreads();

    if (tid < 64) {
        float s = 0.f, s2 = 0.f;
        const float* xr = &Xs[tid*XSTR];
        for (int c = 0; c < CC; c++) { float v = xr[c]; s += v; s2 += v*v; }
        float mu = s * (1.0f/CC);
        float var = s2 * (1.0f/CC) - mu*mu;
        MUs[tid] = mu;
        RIs[tid] = rsqrtf(var + 1e-5f);
    }
    __syncthreads();
    for (int i = tid; i < 64*CC; i += 256) {
        int tt = i >> 7, c = i & 127;
        float v = Xs[tt*XSTR + c];
        v = (v - MUs[tt]) * RIs[tt] * Gs[c] + Bts[c];
        Xs[tt*XSTR + c] = tf32rna(v);
    }
    __syncthreads();

    float acc2[2][4][4];
    #pragma unroll
    for (int n2 = 0; n2 < 2; n2++)
        #pragma unroll
        for (int jn = 0; jn < 4; jn++)
            acc2[n2][jn][0] = acc2[n2][jn][1] = acc2[n2][jn][2] = acc2[n2][jn][3] = 0.f;

    for (int hc = 0; hc < 4; hc++) {
        for (int i = tid; i < 128*16; i += 256) {
            int kk = i >> 4, j4 = i & 15;
            float4 wv = *reinterpret_cast<const float4*>(w1 + kk*HH + hc*64 + j4*4);
            float* d = &Ws[kk*W1STR + j4*4];
            d[0] = tf32rna(wv.x); d[1] = tf32rna(wv.y);
            d[2] = tf32rna(wv.z); d[3] = tf32rna(wv.w);
        }
        __syncthreads();

        float acc[4][4];
        #pragma unroll
        for (int jn = 0; jn < 4; jn++)
            acc[jn][0] = acc[jn][1] = acc[jn][2] = acc[jn][3] = 0.f;
        #pragma unroll
        for (int ks = 0; ks < 16; ks++) {
            uint32_t a[4];
            const float* x0 = &Xs[(mrow+g)*XSTR + ks*8];
            const float* x1 = x0 + 8*XSTR;
            a[0] = fbits(x0[t]); a[1] = fbits(x1[t]);
            a[2] = fbits(x0[t+4]); a[3] = fbits(x1[t+4]);
            #pragma unroll
            for (int jn = 0; jn < 4; jn++) {
                const float* wr = &Ws[(ks*8+t)*W1STR + nhalf + jn*8 + g];
                mma_tf32(acc[jn], a, fbits(wr[0]), fbits(wr[4*W1STR]));
            }
        }
        #pragma unroll
        for (int jn = 0; jn < 4; jn++) {
            int col = nhalf + jn*8 + 2*t;
            float c0 = acc[jn][0] + Bs1[hc*64 + col];
            float c1 = acc[jn][1] + Bs1[hc*64 + col + 1];
            float c2 = acc[jn][2] + Bs1[hc*64 + col];
            float c3 = acc[jn][3] + Bs1[hc*64 + col + 1];
            c0 = (c0 > 0.f) ? c0 : 0.01f*c0;
            c1 = (c1 > 0.f) ? c1 : 0.01f*c1;
            c2 = (c2 > 0.f) ? c2 : 0.01f*c2;
            c3 = (c3 > 0.f) ? c3 : 0.01f*c3;
            float* h0 = &Hcs[(mrow+g)*HCSTR + col];
            float* h1 = &Hcs[(mrow+g+8)*HCSTR + col];
            h0[0] = tf32rna(c0); h0[1] = tf32rna(c1);
            h1[0] = tf32rna(c2); h1[1] = tf32rna(c3);
        }
        __syncthreads();

        for (int i = tid; i < 64*32; i += 256) {
            int kk = i >> 5, j4 = i & 31;
            float4 wv = *reinterpret_cast<const float4*>(w2 + (size_t)(hc*64+kk)*CC + j4*4);
            float* d = &Ws[kk*W2STR + j4*4];
            d[0] = tf32rna(wv.x); d[1] = tf32rna(wv.y);
            d[2] = tf32rna(wv.z); d[3] = tf32rna(wv.w);
        }
        __syncthreads();

        #pragma unroll
        for (int ks = 0; ks < 8; ks++) {
            uint32_t a[4];
            const float* h0 = &Hcs[(mrow+g)*HCSTR + ks*8];
            const float* h1 = h0 + 8*HCSTR;
            a[0] = fbits(h0[t]); a[1] = fbits(h1[t]);
            a[2] = fbits(h0[t+4]); a[3] = fbits(h1[t+4]);
            #pragma unroll
            for (int n2 = 0; n2 < 2; n2++) {
                #pragma unroll
                for (int jn = 0; jn < 4; jn++) {
                    const float* wr = &Ws[(ks*8+t)*W2STR + n2*64 + nhalf + jn*8 + g];
                    mma_tf32(acc2[n2][jn], a, fbits(wr[0]), fbits(wr[4*W2STR]));
                }
            }
        }
        __syncthreads();
    }

    #pragma unroll
    for (int n2 = 0; n2 < 2; n2++) {
        #pragma unroll
        for (int jn = 0; jn < 4; jn++) {
            int col = n2*64 + nhalf + jn*8 + 2*t;
            float* y0 = &Xs[(mrow+g)*XSTR + col];
            float* y1 = &Xs[(mrow+g+8)*XSTR + col];
            y0[0] = acc2[n2][jn][0] + Bs2[col];
            y0[1] = acc2[n2][jn][1] + Bs2[col+1];
            y1[0] = acc2[n2][jn][2] + Bs2[col];
            y1[1] = acc2[n2][jn][3] + Bs2[col+1];
        }
    }
    __syncthreads();

    // ---- grp-specific outputs ----
    if (grp < 2) {
        uint32_t* ob = (grp == 0 ? g_qph : g_kph) + (size_t)gt0*64;
        const float sc = (grp == 0) ? QS2 : 1.0f;
        for (int i = tid; i < 64*64; i += 256) {
            int tt = i >> 6, c2 = (i & 63)*2;
            float lo = Xs[tt*XSTR + c2] * sc;
            float hi = Xs[tt*XSTR + c2 + 1] * sc;
            ob[(size_t)tt*64 + (i & 63)] = cvt2h(hi, lo);
        }
    } else {
        // fp32 token-major (residual for mlp1)
        float* ob = g_vp + (size_t)gt0*CC;
        for (int i = tid; i < 64*CC; i += 256) {
            int tt = i >> 7, c = i & 127;
            ob[i] = Xs[tt*XSTR + c];
        }
        // fp16 d-major transposed: g_vph[b][h][d][s]
        for (int i = tid; i < 128*32; i += 256) {
            int c = i >> 5, tp = (i & 31)*2;
            float lo = Xs[tp*XSTR + c];
            float hi = Xs[(tp+1)*XSTR + c];
            size_t u32idx = ((size_t)(b*NH + (c >> 5))*DD + (c & 31))*(SS/2) + (s0 + tp)/2;
            g_vph[u32idx] = cvt2h(hi, lo);
        }
    }
}

__global__ __launch_bounds__(256, 2)
void qkv_proj_kernel(QKVArgs a)
{
    const int grp = blockIdx.x >> 7;
    const int bx  = blockIdx.x & 127;
    const ProjSet& p = a.ps[grp];
    proj_body256(a.in[grp], p.gam, p.bet, p.w1, p.b1, p.w2, p.b2, grp, bx);
}

// ---- pipelined 256-thread MLP (round-8 known-good) ----
template<bool OUT_CHW>
__global__ __launch_bounds__(256, 1)
void mlp_tc_kernel(int in_sel, const float* __restrict__ w1, const float* __restrict__ b1,
                   const float* __restrict__ w2, const float* __restrict__ b2,
                   int res_sel, float* __restrict__ out_ext, int out_sel)
{
    extern __shared__ float sm[];
    float* Xs  = sm;
    float* Hcs = Xs + 64*XSTR;
    float* WsA = Hcs + 64*HCSTR;
    float* WsB = WsA + 9216;
    float* Bs1 = WsB + 8704;
    float* Bs2 = Bs1 + 256;

    const float* in  = sel_in(in_sel);
    const float* res = sel_in(res_sel);
    float*       out = sel_out(out_sel, out_ext);

    const int tid  = threadIdx.x;
    const int wid  = tid >> 5;
    const int lane = tid & 31;
    const int g    = lane >> 2;
    const int t    = lane & 3;
    const int mrow  = (wid & 3) * 16;
    const int nhalf = (wid >> 2) * 32;

    const int gt0 = blockIdx.x * 64;
    const int b   = gt0 >> 12;
    const int s0  = gt0 & (SS - 1);

    if (tid < 256) Bs1[tid] = b1[tid];
    if (tid < 128) Bs2[tid] = b2[tid];

    float4 wreg[8];
    #pragma unroll
    for (int j = 0; j < 8; j++) {
        int idx = tid + j*256;
        int kk = idx >> 4, j4 = idx & 15;
        wreg[j] = *reinterpret_cast<const float4*>(w1 + kk*HH + j4*4);
    }

    {
        const float* base = in + (size_t)gt0*CC;
        for (int i = tid; i < 64*CC; i += 256) {
            int tt = i >> 7, c = i & 127;
            Xs[tt*XSTR + c] = tf32rna(base[i]);
        }
    }

    float acc2[2][4][4];
    #pragma unroll
    for (int n2 = 0; n2 < 2; n2++)
        #pragma unroll
        for (int jn = 0; jn < 4; jn++)
            acc2[n2][jn][0] = acc2[n2][jn][1] = acc2[n2][jn][2] = acc2[n2][jn][3] = 0.f;

    for (int hc = 0; hc < 4; hc++) {
        #pragma unroll
        for (int j = 0; j < 8; j++) {
            int idx = tid + j*256;
            int kk = idx >> 4, j4 = idx & 15;
            float* d = &WsA[kk*W1STR + j4*4];
            d[0] = tf32rna(wreg[j].x); d[1] = tf32rna(wreg[j].y);
            d[2] = tf32rna(wreg[j].z); d[3] = tf32rna(wreg[j].w);
        }
        #pragma unroll
        for (int j = 0; j < 8; j++) {
            int idx = tid + j*256;
            int kk = idx >> 5, j4 = idx & 31;
            wreg[j] = *reinterpret_cast<const float4*>(w2 + (size_t)(hc*64+kk)*CC + j4*4);
        }
        __syncthreads();

        float acc[4][4];
        #pragma unroll
        for (int jn = 0; jn < 4; jn++)
            acc[jn][0] = acc[jn][1] = acc[jn][2] = acc[jn][3] = 0.f;
        #pragma unroll
        for (int ks = 0; ks < 16; ks++) {
            uint32_t a[4];
            const float* x0 = &Xs[(mrow+g)*XSTR + ks*8];
            const float* x1 = x0 + 8*XSTR;
            a[0] = fbits(x0[t]); a[1] = fbits(x1[t]);
            a[2] = fbits(x0[t+4]); a[3] = fbits(x1[t+4]);
            #pragma unroll
            for (int jn = 0; jn < 4; jn++) {
                const float* wr = &WsA[(ks*8+t)*W1STR + nhalf + jn*8 + g];
                mma_tf32(acc[jn], a, fbits(wr[0]), fbits(wr[4*W1STR]));
            }
        }
        #pragma unroll
        for (int jn = 0; jn < 4; jn++) {
            int col = nhalf + jn*8 + 2*t;
            float c0 = acc[jn][0] + Bs1[hc*64 + col];
            float c1 = acc[jn][1] + Bs1[hc*64 + col + 1];
            float c2 = acc[jn][2] + Bs1[hc*64 + col];
            float c3 = acc[jn][3] + Bs1[hc*64 + col + 1];
            c0 = (c0 > 0.f) ? c0 : 0.01f*c0;
            c1 = (c1 > 0.f) ? c1 : 0.01f*c1;
            c2 = (c2 > 0.f) ? c2 : 0.01f*c2;
            c3 = (c3 > 0.f) ? c3 : 0.01f*c3;
            float* h0 = &Hcs[(mrow+g)*HCSTR + col];
            float* h1 = &Hcs[(mrow+g+8)*HCSTR + col];
            h0[0] = tf32rna(c0); h0[1] = tf32rna(c1);
            h1[0] = tf32rna(c2); h1[1] = tf32rna(c3);
        }
        __syncthreads();

        #pragma unroll
        for (int j = 0; j < 8; j++) {
            int idx = tid + j*256;
            int kk = idx >> 5, j4 = idx & 31;
            float* d = &WsB[kk*W2STR + j4*4];
            d[0] = tf32rna(wreg[j].x); d[1] = tf32rna(wreg[j].y);
            d[2] = tf32rna(wreg[j].z); d[3] = tf32rna(wreg[j].w);
        }
        if (hc < 3) {
            #pragma unroll
            for (int j = 0; j < 8; j++) {
                int idx = tid + j*256;
                int kk = idx >> 4, j4 = idx & 15;
                wreg[j] = *reinterpret_cast<const float4*>(w1 + kk*HH + (hc+1)*64 + j4*4);
            }
        }
        __syncthreads();

        #pragma unroll
        for (int ks = 0; ks < 8; ks++) {
            uint32_t a[4];
            const float* h0 = &Hcs[(mrow+g)*HCSTR + ks*8];
            const float* h1 = h0 + 8*HCSTR;
            a[0] = fbits(h0[t]); a[1] = fbits(h1[t]);
            a[2] = fbits(h0[t+4]); a[3] = fbits(h1[t+4]);
            #pragma unroll
            for (int n2 = 0; n2 < 2; n2++) {
                #pragma unroll
                for (int jn = 0; jn < 4; jn++) {
                    const float* wr = &WsB[(ks*8+t)*W2STR + n2*64 + nhalf + jn*8 + g];
                    mma_tf32(acc2[n2][jn], a, fbits(wr[0]), fbits(wr[4*W2STR]));
                }
            }
        }
        __syncthreads();
    }

    #pragma unroll
    for (int n2 = 0; n2 < 2; n2++) {
        #pragma unroll
        for (int jn = 0; jn < 4; jn++) {
            int col = n2*64 + nhalf + jn*8 + 2*t;
            float* y0 = &Xs[(mrow+g)*XSTR + col];
            float* y1 = &Xs[(mrow+g+8)*XSTR + col];
            y0[0] = acc2[n2][jn][0] + Bs2[col];
            y0[1] = acc2[n2][jn][1] + Bs2[col+1];
            y1[0] = acc2[n2][jn][2] + Bs2[col];
            y1[1] = acc2[n2][jn][3] + Bs2[col+1];
        }
    }
    __syncthreads();

    {
        const float* rb = res + (size_t)gt0*CC;
        for (int i = tid; i < 64*CC; i += 256) {
            int tt = i >> 7, c = i & 127;
            Xs[tt*XSTR + c] += rb[i];
        }
    }
    __syncthreads();

    if (OUT_CHW) {
        float* ob = out + (size_t)b*CC*SS + s0;
        for (int i = tid; i < 64*CC; i += 256) {
            int c = i >> 6, tt = i & 63;
            ob[c*SS + tt] = Xs[tt*XSTR + c];
        }
    } else {
        float* ob = out + (size_t)gt0*CC;
        for (int i = tid; i < 64*CC; i += 256) {
            int tt = i >> 7, c = i & 127;
            ob[i] = Xs[tt*XSTR + c];
        }
    }
}

// ================= fp16 mma.sync flash attention =================
// grid (32, 4, 2), 128 threads (4 warps), BM=128/CTA (2 mfrags/warp), BN=64.
#define KSTRU 20   // u32 per K smem row (40 halves), conflict-free
#define VSTRU 36   // u32 per V smem row (72 halves), conflict-free

__global__ __launch_bounds__(128, 2) void attn_mma_kernel()
{
    __shared__ uint32_t Ks[2][64*KSTRU];   // [key][d] fp16
    __shared__ uint32_t Vs[2][32*VSTRU];   // [d][key] fp16

    const int tid  = threadIdx.x;
    const int wid  = tid >> 5;
    const int lane = tid & 31;
    const int g    = lane >> 2;
    const int t    = lane & 3;
    const int h = blockIdx.y, b = blockIdx.z;
    const int q0 = blockIdx.x * 128;

    const size_t bSS = (size_t)b*SS;
    const uint32_t* kph = g_kph + bSS*64 + h*16;          // row stride 64 u32
    const uint32_t* vph = g_vph + ((size_t)(b*NH + h)*DD)*(SS/2);  // d stride SS/2 u32

    // ---- Q A-fragments (fp16, pre-scaled): qa[mf][ks][4] ----
    uint32_t qa[2][2][4];
    #pragma unroll
    for (int mf = 0; mf < 2; mf++) {
        const int r0 = q0 + wid*32 + mf*16 + g;
        const uint32_t* q0r = g_qph + (bSS + r0)*64 + h*16;
        const uint32_t* q1r = q0r + 8*64;
        #pragma unroll
        for (int ks = 0; ks < 2; ks++) {
            qa[mf][ks][0] = q0r[ks*8 + t];
            qa[mf][ks][1] = q1r[ks*8 + t];
            qa[mf][ks][2] = q0r[ks*8 + t + 4];
            qa[mf][ks][3] = q1r[ks*8 + t + 4];
        }
    }

    float O[2][4][4];
    float m[2][2], l[2][2];
    #pragma unroll
    for (int mf = 0; mf < 2; mf++) {
        #pragma unroll
        for (int j = 0; j < 4; j++)
            #pragma unroll
            for (int i = 0; i < 4; i++) O[mf][j][i] = 0.f;
        m[mf][0] = m[mf][1] = -1e30f;
        l[mf][0] = l[mf][1] = 0.f;
    }

    // cp.async tile loader: K 64 rows x 64B (4 chunks), V 32 rows x 128B (8 chunks)
    auto cp_tile = [&](int tile, int buf) {
        #pragma unroll
        for (int r = 0; r < 2; r++) {
            int idx = tid + r*128;           // 0..255
            {
                int row = idx >> 2, ch = idx & 3;
                const uint32_t* src = kph + (size_t)(tile*64 + row)*64 + ch*4;
                uint32_t d = (uint32_t)__cvta_generic_to_shared(&Ks[buf][row*KSTRU + ch*4]);
                asm volatile("cp.async.ca.shared.global [%0], [%1], 16;" :: "r"(d), "l"(src));
            }
            {
                int dd = idx >> 3, ch = idx & 7;
                const uint32_t* src = vph + (size_t)dd*(SS/2) + tile*32 + ch*4;
                uint32_t d = (uint32_t)__cvta_generic_to_shared(&Vs[buf][dd*VSTRU + ch*4]);
                asm volatile("cp.async.ca.shared.global [%0], [%1], 16;" :: "r"(d), "l"(src));
            }
        }
        asm volatile("cp.async.commit_group;" ::: "memory");
    };

    cp_tile(0, 0);

    for (int tile = 0; tile < SS/64; tile++) {
        const int buf = tile & 1;
        if (tile + 1 < SS/64) {
            cp_tile(tile + 1, buf ^ 1);
            asm volatile("cp.async.wait_group 1;" ::: "memory");
        } else {
            asm volatile("cp.async.wait_group 0;" ::: "memory");
        }
        __syncthreads();

        // ---- S = Q @ K^T : 8 n-frags, 2 k-steps; B shared across mfrags ----
        float s[2][8][4];
        #pragma unroll
        for (int jn = 0; jn < 8; jn++) {
            #pragma unroll
            for (int mf = 0; mf < 2; mf++)
                s[mf][jn][0] = s[mf][jn][1] = s[mf][jn][2] = s[mf][jn][3] = 0.f;
            const uint32_t* kr = &Ks[buf][(jn*8 + g)*KSTRU];
            #pragma unroll
            for (int ks = 0; ks < 2; ks++) {
                uint32_t b0 = kr[ks*8 + t];
                uint32_t b1 = kr[ks*8 + t + 4];
                mma_f16(s[0][jn], qa[0][ks], b0, b1);
                mma_f16(s[1][jn], qa[1][ks], b0, b1);
            }
        }

        // ---- online softmax (log2 domain; Q pre-scaled) ----
        float corr[2][2];
        #pragma unroll
        for (int mf = 0; mf < 2; mf++) {
            float mt0 = s[mf][0][0], mt1 = s[mf][0][2];
            #pragma unroll
            for (int jn = 0; jn < 8; jn++) {
                mt0 = fmaxf(mt0, fmaxf(s[mf][jn][0], s[mf][jn][1]));
                mt1 = fmaxf(mt1, fmaxf(s[mf][jn][2], s[mf][jn][3]));
            }
            mt0 = fmaxf(mt0, __shfl_xor_sync(0xffffffffu, mt0, 1));
            mt0 = fmaxf(mt0, __shfl_xor_sync(0xffffffffu, mt0, 2));
            mt1 = fmaxf(mt1, __shfl_xor_sync(0xffffffffu, mt1, 1));
            mt1 = fmaxf(mt1, __shfl_xor_sync(0xffffffffu, mt1, 2));
            const float mn0 = fmaxf(m[mf][0], mt0), mn1 = fmaxf(m[mf][1], mt1);
            corr[mf][0] = fexp2(m[mf][0] - mn0);
            corr[mf][1] = fexp2(m[mf][1] - mn1);
            m[mf][0] = mn0; m[mf][1] = mn1;
            float ls0 = 0.f, ls1 = 0.f;
            #pragma unroll
            for (int jn = 0; jn < 8; jn++) {
                s[mf][jn][0] = fexp2(s[mf][jn][0] - mn0); ls0 += s[mf][jn][0];
                s[mf][jn][1] = fexp2(s[mf][jn][1] - mn0); ls0 += s[mf][jn][1];
                s[mf][jn][2] = fexp2(s[mf][jn][2] - mn1); ls1 += s[mf][jn][2];
                s[mf][jn][3] = fexp2(s[mf][jn][3] - mn1); ls1 += s[mf][jn][3];
            }
            l[mf][0] = l[mf][0]*corr[mf][0] + ls0;
            l[mf][1] = l[mf][1]*corr[mf][1] + ls1;
            #pragma unroll
            for (int j = 0; j < 4; j++) {
                O[mf][j][0] *= corr[mf][0]; O[mf][j][1] *= corr[mf][0];
                O[mf][j][2] *= corr[mf][1]; O[mf][j][3] *= corr[mf][1];
            }
        }

        // ---- O += P @ V : P packed to fp16 A-frags directly from C layout ----
        #pragma unroll
        for (int ks = 0; ks < 4; ks++) {
            uint32_t pa[2][4];
            #pragma unroll
            for (int mf = 0; mf < 2; mf++) {
                pa[mf][0] = cvt2h(s[mf][2*ks  ][1], s[mf][2*ks  ][0]);
                pa[mf][1] = cvt2h(s[mf][2*ks  ][3], s[mf][2*ks  ][2]);
                pa[mf][2] = cvt2h(s[mf][2*ks+1][1], s[mf][2*ks+1][0]);
                pa[mf][3] = cvt2h(s[mf][2*ks+1][3], s[mf][2*ks+1][2]);
            }
            #pragma unroll
            for (int jn = 0; jn < 4; jn++) {
                const uint32_t* vr = &Vs[buf][(jn*8 + g)*VSTRU + ks*8];
                uint32_t b0 = vr[t];
                uint32_t b1 = vr[t + 4];
                mma_f16(O[0][jn], pa[0], b0, b1);
                mma_f16(O[1][jn], pa[1], b0, b1);
            }
        }
        __syncthreads();
    }

    // ---- epilogue: reduce l, normalize, write fp32 ----
    #pragma unroll
    for (int mf = 0; mf < 2; mf++) {
        float l0 = l[mf][0], l1 = l[mf][1];
        l0 += __shfl_xor_sync(0xffffffffu, l0, 1);
        l0 += __shfl_xor_sync(0xffffffffu, l0, 2);
        l1 += __shfl_xor_sync(0xffffffffu, l1, 1);
        l1 += __shfl_xor_sync(0xffffffffu, l1, 2);
        const float inv0 = 1.0f / l0, inv1 = 1.0f / l1;
        const int r0 = q0 + wid*32 + mf*16 + g;
        float* o0 = g_x + (bSS + r0)*CC + h*DD;
        float* o1 = o0 + 8*CC;
        #pragma unroll
        for (int jn = 0; jn < 4; jn++) {
            float2 u0 = make_float2(O[mf][jn][0]*inv0, O[mf][jn][1]*inv0);
            float2 u1 = make_float2(O[mf][jn][2]*inv1, O[mf][jn][3]*inv1);
            *reinterpret_cast<float2*>(o0 + jn*8 + 2*t) = u0;
            *reinterpret_cast<float2*>(o1 + jn*8 + 2*t) = u1;
        }
    }
}

// ---------------- launcher ----------------
extern "C" void kernel_launch(void* const* d_in, const int* in_sizes, int n_in,
                              void* d_out, int out_size)
{
    (void)in_sizes; (void)n_in; (void)out_size;
    const float* q = (const float*)d_in[0];
    const float* k = (const float*)d_in[1];
    const float* v = (const float*)d_in[2];
    float* out = (float*)d_out;

    QKVArgs qa;
    qa.in[0] = q; qa.in[1] = k; qa.in[2] = v;
    qa.ps[0] = ProjSet{ (const float*)d_in[3], (const float*)d_in[4],
                        (const float*)d_in[5], (const float*)d_in[6],
                        (const float*)d_in[7], (const float*)d_in[8] };
    qa.ps[1] = ProjSet{ (const float*)d_in[9], (const float*)d_in[10],
                        (const float*)d_in[11], (const float*)d_in[12],
                        (const float*)d_in[13], (const float*)d_in[14] };
    qa.ps[2] = ProjSet{ (const float*)d_in[15], (const float*)d_in[16],
                        (const float*)d_in[17], (const float*)d_in[18],
                        (const float*)d_in[19], (const float*)d_in[20] };

    const float* m1_w1 = (const float*)d_in[21];
    const float* m1_b1 = (const float*)d_in[22];
    const float* m1_w2 = (const float*)d_in[23];
    const float* m1_b2 = (const float*)d_in[24];
    const float* m2_w1 = (const float*)d_in[25];
    const float* m2_b1 = (const float*)d_in[26];
    const float* m2_w2 = (const float*)d_in[27];
    const float* m2_b2 = (const float*)d_in[28];

    cudaFuncSetAttribute(qkv_proj_kernel,
                         cudaFuncAttributeMaxDynamicSharedMemorySize, PROJ_SMEM_BYTES);
    cudaFuncSetAttribute(mlp_tc_kernel<false>,
                         cudaFuncAttributeMaxDynamicSharedMemorySize, MLP_SMEM_BYTES);
    cudaFuncSetAttribute(mlp_tc_kernel<true>,
                         cudaFuncAttributeMaxDynamicSharedMemorySize, MLP_SMEM_BYTES);

    // fused q/k/v projections -> g_qph/g_kph/(g_vp + g_vph)
    qkv_proj_kernel<<<384, 256, PROJ_SMEM_BYTES>>>(qa);

    // fp16 flash attention -> g_x
    attn_mma_kernel<<<dim3(SS/128, NH, BB), 128>>>();

    // rs1 = vp + mlp1(x) -> g_r1
    mlp_tc_kernel<false><<<128, 256, MLP_SMEM_BYTES>>>(3, m1_w1, m1_b1, m1_w2, m1_b2, 2, nullptr, 4);

    // rs2 = rs1 + mlp2(rs1) -> out (CHW)
    mlp_tc_kernel<true><<<128, 256, MLP_SMEM_BYTES>>>(4, m2_w1, m2_b1, m2_w2, m2_b2, 4, out, -1);
}

// round 10
// speedup vs baseline: 1.5214x; 1.0382x over previous
#include <cuda_runtime.h>
#include <math.h>
#include <stdint.h>

#define BB 2
#define CC 128
#define HH 256      // 2*C
#define SS 4096     // 64*64 tokens
#define NH 4
#define DD 32       // head dim

#define QS 0.1767766952966369f   // 1/sqrt(32)
#define QS2 (QS * 1.4426950408889634f)   // fold log2(e) for ex2-domain softmax

// ---------------- scratch (no allocation allowed) ----------------
__device__ uint32_t g_qph[BB*SS*CC/2];   // fp16 Q, token-major, pre-scaled by QS*log2e
__device__ uint32_t g_kph[BB*SS*CC/2];   // fp16 K, token-major
__device__ uint32_t g_vph[BB*SS*CC/2];   // fp16 V, d-major: [b][h][d][s]
__device__ float g_vp[BB*SS*CC];         // fp32 V (residual for mlp1)
__device__ float g_x [BB*SS*CC];         // attention output

// tf32 mma m16n8k8 row.col
__device__ __forceinline__ void mma_tf32(float* c, const uint32_t* a, uint32_t b0, uint32_t b1) {
    asm volatile(
        "mma.sync.aligned.m16n8k8.row.col.f32.tf32.tf32.f32 "
        "{%0,%1,%2,%3}, {%4,%5,%6,%7}, {%8,%9}, {%0,%1,%2,%3};"
        : "+f"(c[0]), "+f"(c[1]), "+f"(c[2]), "+f"(c[3])
        : "r"(a[0]), "r"(a[1]), "r"(a[2]), "r"(a[3]), "r"(b0), "r"(b1));
}
// fp16 mma m16n8k16 row.col, fp32 accumulate
__device__ __forceinline__ void mma_f16(float* c, const uint32_t* a, uint32_t b0, uint32_t b1) {
    asm volatile(
        "mma.sync.aligned.m16n8k16.row.col.f32.f16.f16.f32 "
        "{%0,%1,%2,%3}, {%4,%5,%6,%7}, {%8,%9}, {%0,%1,%2,%3};"
        : "+f"(c[0]), "+f"(c[1]), "+f"(c[2]), "+f"(c[3])
        : "r"(a[0]), "r"(a[1]), "r"(a[2]), "r"(a[3]), "r"(b0), "r"(b1));
}
__device__ __forceinline__ float tf32rna(float x) {
    uint32_t r;
    asm("cvt.rna.tf32.f32 %0, %1;" : "=r"(r) : "f"(x));
    return __uint_as_float(r);
}
__device__ __forceinline__ uint32_t fbits(float x) { return __float_as_uint(x); }
__device__ __forceinline__ float fexp2(float x) {
    float r;
    asm("ex2.approx.f32 %0, %1;" : "=f"(r) : "f"(x));
    return r;
}
__device__ __forceinline__ uint32_t cvt2h(float hi, float lo) {
    uint32_t r;
    asm("cvt.rn.f16x2.f32 %0, %1, %2;" : "=r"(r) : "f"(hi), "f"(lo));
    return r;
}

// ================= projection smem layout =================
#define XSTR 132
#define HCSTR 68
#define W1STR 72
#define W2STR 136
#define PROJ_SMEM_FLOATS (64*XSTR + 64*HCSTR + 9216 + 256 + 128 + 128 + 128 + 64 + 64)
#define PROJ_SMEM_BYTES (PROJ_SMEM_FLOATS*4)
#define MLP_SMEM_FLOATS (64*XSTR + 64*HCSTR + 9216 + 8704 + 256 + 128)
#define MLP_SMEM_BYTES (MLP_SMEM_FLOATS*4)

struct ProjSet { const float *gam, *bet, *w1, *b1, *w2, *b2; };
struct QKVArgs { const float* in[3]; ProjSet ps[3]; };
struct MlpArgs { const float *w1a, *b1a, *w2a, *b2a, *w1b, *b1b, *w2b, *b2b; };

// ---- 256-thread qkv body: CHW input + LN, grp-specific fp16 outputs ----
__device__ __forceinline__ void proj_body256(
    const float* __restrict__ in, const float* __restrict__ gamma, const float* __restrict__ beta,
    const float* __restrict__ w1, const float* __restrict__ b1,
    const float* __restrict__ w2, const float* __restrict__ b2,
    int grp, int bx)
{
    extern __shared__ float sm[];
    float* Xs  = sm;
    float* Hcs = Xs + 64*XSTR;
    float* Ws  = Hcs + 64*HCSTR;
    float* Bs1 = Ws + 9216;
    float* Bs2 = Bs1 + 256;
    float* Gs  = Bs2 + 128;
    float* Bts = Gs + 128;
    float* MUs = Bts + 128;
    float* RIs = MUs + 64;

    const int tid  = threadIdx.x;
    const int wid  = tid >> 5;
    const int lane = tid & 31;
    const int g    = lane >> 2;
    const int t    = lane & 3;
    const int mrow  = (wid & 3) * 16;
    const int nhalf = (wid >> 2) * 32;

    const int gt0 = bx * 64;
    const int b   = gt0 >> 12;
    const int s0  = gt0 & (SS - 1);

    if (tid < 256) Bs1[tid] = b1[tid];
    if (tid < 128) { Bs2[tid] = b2[tid]; Gs[tid] = gamma[tid]; Bts[tid] = beta[tid]; }

    {
        const float* base = in + (size_t)b*CC*SS + s0;
        for (int i = tid; i < 64*CC; i += 256) {
            int c = i >> 6, tt = i & 63;
            Xs[tt*XSTR + c] = base[c*SS + tt];
        }
    }
    __syncthreads();

    if (tid < 64) {
        float s = 0.f, s2 = 0.f;
        const float* xr = &Xs[tid*XSTR];
        for (int c = 0; c < CC; c++) { float v = xr[c]; s += v; s2 += v*v; }
        float mu = s * (1.0f/CC);
        float var = s2 * (1.0f/CC) - mu*mu;
        MUs[tid] = mu;
        RIs[tid] = rsqrtf(var + 1e-5f);
    }
    __syncthreads();
    for (int i = tid; i < 64*CC; i += 256) {
        int tt = i >> 7, c = i & 127;
        float v = Xs[tt*XSTR + c];
        v = (v - MUs[tt]) * RIs[tt] * Gs[c] + Bts[c];
        Xs[tt*XSTR + c] = tf32rna(v);
    }
    __syncthreads();

    float acc2[2][4][4];
    #pragma unroll
    for (int n2 = 0; n2 < 2; n2++)
        #pragma unroll
        for (int jn = 0; jn < 4; jn++)
            acc2[n2][jn][0] = acc2[n2][jn][1] = acc2[n2][jn][2] = acc2[n2][jn][3] = 0.f;

    for (int hc = 0; hc < 4; hc++) {
        for (int i = tid; i < 128*16; i += 256) {
            int kk = i >> 4, j4 = i & 15;
            float4 wv = *reinterpret_cast<const float4*>(w1 + kk*HH + hc*64 + j4*4);
            float* d = &Ws[kk*W1STR + j4*4];
            d[0] = tf32rna(wv.x); d[1] = tf32rna(wv.y);
            d[2] = tf32rna(wv.z); d[3] = tf32rna(wv.w);
        }
        __syncthreads();

        float acc[4][4];
        #pragma unroll
        for (int jn = 0; jn < 4; jn++)
            acc[jn][0] = acc[jn][1] = acc[jn][2] = acc[jn][3] = 0.f;
        #pragma unroll
        for (int ks = 0; ks < 16; ks++) {
            uint32_t a[4];
            const float* x0 = &Xs[(mrow+g)*XSTR + ks*8];
            const float* x1 = x0 + 8*XSTR;
            a[0] = fbits(x0[t]); a[1] = fbits(x1[t]);
            a[2] = fbits(x0[t+4]); a[3] = fbits(x1[t+4]);
            #pragma unroll
            for (int jn = 0; jn < 4; jn++) {
                const float* wr = &Ws[(ks*8+t)*W1STR + nhalf + jn*8 + g];
                mma_tf32(acc[jn], a, fbits(wr[0]), fbits(wr[4*W1STR]));
            }
        }
        #pragma unroll
        for (int jn = 0; jn < 4; jn++) {
            int col = nhalf + jn*8 + 2*t;
            float c0 = acc[jn][0] + Bs1[hc*64 + col];
            float c1 = acc[jn][1] + Bs1[hc*64 + col + 1];
            float c2 = acc[jn][2] + Bs1[hc*64 + col];
            float c3 = acc[jn][3] + Bs1[hc*64 + col + 1];
            c0 = (c0 > 0.f) ? c0 : 0.01f*c0;
            c1 = (c1 > 0.f) ? c1 : 0.01f*c1;
            c2 = (c2 > 0.f) ? c2 : 0.01f*c2;
            c3 = (c3 > 0.f) ? c3 : 0.01f*c3;
            float* h0 = &Hcs[(mrow+g)*HCSTR + col];
            float* h1 = &Hcs[(mrow+g+8)*HCSTR + col];
            h0[0] = tf32rna(c0); h0[1] = tf32rna(c1);
            h1[0] = tf32rna(c2); h1[1] = tf32rna(c3);
        }
        __syncthreads();

        for (int i = tid; i < 64*32; i += 256) {
            int kk = i >> 5, j4 = i & 31;
            float4 wv = *reinterpret_cast<const float4*>(w2 + (size_t)(hc*64+kk)*CC + j4*4);
            float* d = &Ws[kk*W2STR + j4*4];
            d[0] = tf32rna(wv.x); d[1] = tf32rna(wv.y);
            d[2] = tf32rna(wv.z); d[3] = tf32rna(wv.w);
        }
        __syncthreads();

        #pragma unroll
        for (int ks = 0; ks < 8; ks++) {
            uint32_t a[4];
            const float* h0 = &Hcs[(mrow+g)*HCSTR + ks*8];
            const float* h1 = h0 + 8*HCSTR;
            a[0] = fbits(h0[t]); a[1] = fbits(h1[t]);
            a[2] = fbits(h0[t+4]); a[3] = fbits(h1[t+4]);
            #pragma unroll
            for (int n2 = 0; n2 < 2; n2++) {
                #pragma unroll
                for (int jn = 0; jn < 4; jn++) {
                    const float* wr = &Ws[(ks*8+t)*W2STR + n2*64 + nhalf + jn*8 + g];
                    mma_tf32(acc2[n2][jn], a, fbits(wr[0]), fbits(wr[4*W2STR]));
                }
            }
        }
        __syncthreads();
    }

    #pragma unroll
    for (int n2 = 0; n2 < 2; n2++) {
        #pragma unroll
        for (int jn = 0; jn < 4; jn++) {
            int col = n2*64 + nhalf + jn*8 + 2*t;
            float* y0 = &Xs[(mrow+g)*XSTR + col];
            float* y1 = &Xs[(mrow+g+8)*XSTR + col];
            y0[0] = acc2[n2][jn][0] + Bs2[col];
            y0[1] = acc2[n2][jn][1] + Bs2[col+1];
            y1[0] = acc2[n2][jn][2] + Bs2[col];
            y1[1] = acc2[n2][jn][3] + Bs2[col+1];
        }
    }
    __syncthreads();

    // ---- grp-specific outputs ----
    if (grp < 2) {
        uint32_t* ob = (grp == 0 ? g_qph : g_kph) + (size_t)gt0*64;
        const float sc = (grp == 0) ? QS2 : 1.0f;
        for (int i = tid; i < 64*64; i += 256) {
            int tt = i >> 6, c2 = (i & 63)*2;
            float lo = Xs[tt*XSTR + c2] * sc;
            float hi = Xs[tt*XSTR + c2 + 1] * sc;
            ob[(size_t)tt*64 + (i & 63)] = cvt2h(hi, lo);
        }
    } else {
        float* ob = g_vp + (size_t)gt0*CC;
        for (int i = tid; i < 64*CC; i += 256) {
            int tt = i >> 7, c = i & 127;
            ob[i] = Xs[tt*XSTR + c];
        }
        for (int i = tid; i < 128*32; i += 256) {
            int c = i >> 5, tp = (i & 31)*2;
            float lo = Xs[tp*XSTR + c];
            float hi = Xs[(tp+1)*XSTR + c];
            size_t u32idx = ((size_t)(b*NH + (c >> 5))*DD + (c & 31))*(SS/2) + (s0 + tp)/2;
            g_vph[u32idx] = cvt2h(hi, lo);
        }
    }
}

__global__ __launch_bounds__(256, 2)
void qkv_proj_kernel(QKVArgs a)
{
    const int grp = blockIdx.x >> 7;
    const int bx  = blockIdx.x & 127;
    const ProjSet& p = a.ps[grp];
    proj_body256(a.in[grp], p.gam, p.bet, p.w1, p.b1, p.w2, p.b2, grp, bx);
}

// ---- fused MLP1+MLP2: rs2 = rs1 + mlp2(rs1), rs1 = vp + mlp1(x); one CTA per 64 tokens ----
__global__ __launch_bounds__(256, 1)
void mlp_fused_kernel(MlpArgs ag, float* __restrict__ out)
{
    extern __shared__ float sm[];
    float* Xs  = sm;                    // [64][132]
    float* Hcs = Xs + 64*XSTR;          // [64][68]
    float* WsA = Hcs + 64*HCSTR;        // [128][72]
    float* WsB = WsA + 9216;            // [64][136]
    float* Bs1 = WsB + 8704;            // [256]
    float* Bs2 = Bs1 + 256;             // [128]

    const int tid  = threadIdx.x;
    const int wid  = tid >> 5;
    const int lane = tid & 31;
    const int g    = lane >> 2;
    const int t    = lane & 3;
    const int mrow  = (wid & 3) * 16;
    const int nhalf = (wid >> 2) * 32;

    const int gt0 = blockIdx.x * 64;
    const int b   = gt0 >> 12;
    const int s0  = gt0 & (SS - 1);

    float4 wreg[8];
    // prefetch m1_w1 chunk 0
    #pragma unroll
    for (int j = 0; j < 8; j++) {
        int idx = tid + j*256;
        int kk = idx >> 4, j4 = idx & 15;
        wreg[j] = *reinterpret_cast<const float4*>(ag.w1a + kk*HH + j4*4);
    }

    // load X (attention output) -> tf32 in Xs
    {
        const float* base = g_x + (size_t)gt0*CC;
        for (int i = tid; i < 64*CC; i += 256) {
            int tt = i >> 7, c = i & 127;
            Xs[tt*XSTR + c] = tf32rna(base[i]);
        }
    }

    #pragma unroll 1
    for (int mm = 0; mm < 2; mm++) {
        const float* w1 = mm ? ag.w1b : ag.w1a;
        const float* b1 = mm ? ag.b1b : ag.b1a;
        const float* w2 = mm ? ag.w2b : ag.w2a;
        const float* b2 = mm ? ag.b2b : ag.b2a;
        const float* w1_next = mm ? nullptr : ag.w1b;

        if (tid < 256) Bs1[tid] = b1[tid];
        if (tid < 128) Bs2[tid] = b2[tid];

        float acc2[2][4][4];
        #pragma unroll
        for (int n2 = 0; n2 < 2; n2++)
            #pragma unroll
            for (int jn = 0; jn < 4; jn++)
                acc2[n2][jn][0] = acc2[n2][jn][1] = acc2[n2][jn][2] = acc2[n2][jn][3] = 0.f;

        #pragma unroll 1
        for (int hc = 0; hc < 4; hc++) {
            // store W1 regs -> WsA, prefetch W2 chunk hc
            #pragma unroll
            for (int j = 0; j < 8; j++) {
                int idx = tid + j*256;
                int kk = idx >> 4, j4 = idx & 15;
                float* d = &WsA[kk*W1STR + j4*4];
                d[0] = tf32rna(wreg[j].x); d[1] = tf32rna(wreg[j].y);
                d[2] = tf32rna(wreg[j].z); d[3] = tf32rna(wreg[j].w);
            }
            #pragma unroll
            for (int j = 0; j < 8; j++) {
                int idx = tid + j*256;
                int kk = idx >> 5, j4 = idx & 31;
                wreg[j] = *reinterpret_cast<const float4*>(w2 + (size_t)(hc*64+kk)*CC + j4*4);
            }
            __syncthreads();

            // stage 1: Hc = leaky(X @ W1c + b1c); rna applied in A-load (identity when X already tf32)
            float acc[4][4];
            #pragma unroll
            for (int jn = 0; jn < 4; jn++)
                acc[jn][0] = acc[jn][1] = acc[jn][2] = acc[jn][3] = 0.f;
            #pragma unroll
            for (int ks = 0; ks < 16; ks++) {
                uint32_t a[4];
                const float* x0 = &Xs[(mrow+g)*XSTR + ks*8];
                const float* x1 = x0 + 8*XSTR;
                a[0] = fbits(tf32rna(x0[t]));   a[1] = fbits(tf32rna(x1[t]));
                a[2] = fbits(tf32rna(x0[t+4])); a[3] = fbits(tf32rna(x1[t+4]));
                #pragma unroll
                for (int jn = 0; jn < 4; jn++) {
                    const float* wr = &WsA[(ks*8+t)*W1STR + nhalf + jn*8 + g];
                    mma_tf32(acc[jn], a, fbits(wr[0]), fbits(wr[4*W1STR]));
                }
            }
            #pragma unroll
            for (int jn = 0; jn < 4; jn++) {
                int col = nhalf + jn*8 + 2*t;
                float c0 = acc[jn][0] + Bs1[hc*64 + col];
                float c1 = acc[jn][1] + Bs1[hc*64 + col + 1];
                float c2 = acc[jn][2] + Bs1[hc*64 + col];
                float c3 = acc[jn][3] + Bs1[hc*64 + col + 1];
                c0 = (c0 > 0.f) ? c0 : 0.01f*c0;
                c1 = (c1 > 0.f) ? c1 : 0.01f*c1;
                c2 = (c2 > 0.f) ? c2 : 0.01f*c2;
                c3 = (c3 > 0.f) ? c3 : 0.01f*c3;
                float* h0 = &Hcs[(mrow+g)*HCSTR + col];
                float* h1 = &Hcs[(mrow+g+8)*HCSTR + col];
                h0[0] = tf32rna(c0); h0[1] = tf32rna(c1);
                h1[0] = tf32rna(c2); h1[1] = tf32rna(c3);
            }
            __syncthreads();

            // store W2 regs -> WsB, prefetch next W1 chunk (this mlp hc+1, or next mlp chunk 0)
            #pragma unroll
            for (int j = 0; j < 8; j++) {
                int idx = tid + j*256;
                int kk = idx >> 5, j4 = idx & 31;
                float* d = &WsB[kk*W2STR + j4*4];
                d[0] = tf32rna(wreg[j].x); d[1] = tf32rna(wreg[j].y);
                d[2] = tf32rna(wreg[j].z); d[3] = tf32rna(wreg[j].w);
            }
            if (hc < 3) {
                #pragma unroll
                for (int j = 0; j < 8; j++) {
                    int idx = tid + j*256;
                    int kk = idx >> 4, j4 = idx & 15;
                    wreg[j] = *reinterpret_cast<const float4*>(w1 + kk*HH + (hc+1)*64 + j4*4);
                }
            } else if (w1_next) {
                #pragma unroll
                for (int j = 0; j < 8; j++) {
                    int idx = tid + j*256;
                    int kk = idx >> 4, j4 = idx & 15;
                    wreg[j] = *reinterpret_cast<const float4*>(w1_next + kk*HH + j4*4);
                }
            }
            __syncthreads();

            // stage 2 partial
            #pragma unroll
            for (int ks = 0; ks < 8; ks++) {
                uint32_t a[4];
                const float* h0 = &Hcs[(mrow+g)*HCSTR + ks*8];
                const float* h1 = h0 + 8*HCSTR;
                a[0] = fbits(h0[t]); a[1] = fbits(h1[t]);
                a[2] = fbits(h0[t+4]); a[3] = fbits(h1[t+4]);
                #pragma unroll
                for (int n2 = 0; n2 < 2; n2++) {
                    #pragma unroll
                    for (int jn = 0; jn < 4; jn++) {
                        const float* wr = &WsB[(ks*8+t)*W2STR + n2*64 + nhalf + jn*8 + g];
                        mma_tf32(acc2[n2][jn], a, fbits(wr[0]), fbits(wr[4*W2STR]));
                    }
                }
            }
            __syncthreads();
        }

        if (mm == 0) {
            // rs1 = Y1 + b2 + vp   (fp32 in Xs)
            #pragma unroll
            for (int n2 = 0; n2 < 2; n2++) {
                #pragma unroll
                for (int jn = 0; jn < 4; jn++) {
                    int col = n2*64 + nhalf + jn*8 + 2*t;
                    float* y0 = &Xs[(mrow+g)*XSTR + col];
                    float* y1 = &Xs[(mrow+g+8)*XSTR + col];
                    y0[0] = acc2[n2][jn][0] + Bs2[col];
                    y0[1] = acc2[n2][jn][1] + Bs2[col+1];
                    y1[0] = acc2[n2][jn][2] + Bs2[col];
                    y1[1] = acc2[n2][jn][3] + Bs2[col+1];
                }
            }
            __syncthreads();
            const float* rb = g_vp + (size_t)gt0*CC;
            for (int i = tid; i < 64*CC; i += 256) {
                int tt = i >> 7, c = i & 127;
                Xs[tt*XSTR + c] += rb[i];
            }
            __syncthreads();
        } else {
            // rs2 = Y2 + b2 + rs1 -> CHW out
            #pragma unroll
            for (int n2 = 0; n2 < 2; n2++) {
                #pragma unroll
                for (int jn = 0; jn < 4; jn++) {
                    int col = n2*64 + nhalf + jn*8 + 2*t;
                    float* y0 = &Xs[(mrow+g)*XSTR + col];
                    float* y1 = &Xs[(mrow+g+8)*XSTR + col];
                    y0[0] += acc2[n2][jn][0] + Bs2[col];
                    y0[1] += acc2[n2][jn][1] + Bs2[col+1];
                    y1[0] += acc2[n2][jn][2] + Bs2[col];
                    y1[1] += acc2[n2][jn][3] + Bs2[col+1];
                }
            }
            __syncthreads();
            float* ob = out + (size_t)b*CC*SS + s0;
            for (int i = tid; i < 64*CC; i += 256) {
                int c = i >> 6, tt = i & 63;
                ob[c*SS + tt] = Xs[tt*XSTR + c];
            }
        }
    }
}

// ================= fp16 mma.sync flash attention (unchanged, known-good) =================
#define KSTRU 20
#define VSTRU 36

__global__ __launch_bounds__(128, 2) void attn_mma_kernel()
{
    __shared__ uint32_t Ks[2][64*KSTRU];
    __shared__ uint32_t Vs[2][32*VSTRU];

    const int tid  = threadIdx.x;
    const int wid  = tid >> 5;
    const int lane = tid & 31;
    const int g    = lane >> 2;
    const int t    = lane & 3;
    const int h = blockIdx.y, b = blockIdx.z;
    const int q0 = blockIdx.x * 128;

    const size_t bSS = (size_t)b*SS;
    const uint32_t* kph = g_kph + bSS*64 + h*16;
    const uint32_t* vph = g_vph + ((size_t)(b*NH + h)*DD)*(SS/2);

    uint32_t qa[2][2][4];
    #pragma unroll
    for (int mf = 0; mf < 2; mf++) {
        const int r0 = q0 + wid*32 + mf*16 + g;
        const uint32_t* q0r = g_qph + (bSS + r0)*64 + h*16;
        const uint32_t* q1r = q0r + 8*64;
        #pragma unroll
        for (int ks = 0; ks < 2; ks++) {
            qa[mf][ks][0] = q0r[ks*8 + t];
            qa[mf][ks][1] = q1r[ks*8 + t];
            qa[mf][ks][2] = q0r[ks*8 + t + 4];
            qa[mf][ks][3] = q1r[ks*8 + t + 4];
        }
    }

    float O[2][4][4];
    float m[2][2], l[2][2];
    #pragma unroll
    for (int mf = 0; mf < 2; mf++) {
        #pragma unroll
        for (int j = 0; j < 4; j++)
            #pragma unroll
            for (int i = 0; i < 4; i++) O[mf][j][i] = 0.f;
        m[mf][0] = m[mf][1] = -1e30f;
        l[mf][0] = l[mf][1] = 0.f;
    }

    auto cp_tile = [&](int tile, int buf) {
        #pragma unroll
        for (int r = 0; r < 2; r++) {
            int idx = tid + r*128;
            {
                int row = idx >> 2, ch = idx & 3;
                const uint32_t* src = kph + (size_t)(tile*64 + row)*64 + ch*4;
                uint32_t d = (uint32_t)__cvta_generic_to_shared(&Ks[buf][row*KSTRU + ch*4]);
                asm volatile("cp.async.ca.shared.global [%0], [%1], 16;" :: "r"(d), "l"(src));
            }
            {
                int dd = idx >> 3, ch = idx & 7;
                const uint32_t* src = vph + (size_t)dd*(SS/2) + tile*32 + ch*4;
                uint32_t d = (uint32_t)__cvta_generic_to_shared(&Vs[buf][dd*VSTRU + ch*4]);
                asm volatile("cp.async.ca.shared.global [%0], [%1], 16;" :: "r"(d), "l"(src));
            }
        }
        asm volatile("cp.async.commit_group;" ::: "memory");
    };

    cp_tile(0, 0);

    for (int tile = 0; tile < SS/64; tile++) {
        const int buf = tile & 1;
        if (tile + 1 < SS/64) {
            cp_tile(tile + 1, buf ^ 1);
            asm volatile("cp.async.wait_group 1;" ::: "memory");
        } else {
            asm volatile("cp.async.wait_group 0;" ::: "memory");
        }
        __syncthreads();

        float s[2][8][4];
        #pragma unroll
        for (int jn = 0; jn < 8; jn++) {
            #pragma unroll
            for (int mf = 0; mf < 2; mf++)
                s[mf][jn][0] = s[mf][jn][1] = s[mf][jn][2] = s[mf][jn][3] = 0.f;
            const uint32_t* kr = &Ks[buf][(jn*8 + g)*KSTRU];
            #pragma unroll
            for (int ks = 0; ks < 2; ks++) {
                uint32_t b0 = kr[ks*8 + t];
                uint32_t b1 = kr[ks*8 + t + 4];
                mma_f16(s[0][jn], qa[0][ks], b0, b1);
                mma_f16(s[1][jn], qa[1][ks], b0, b1);
            }
        }

        float corr[2][2];
        #pragma unroll
        for (int mf = 0; mf < 2; mf++) {
            float mt0 = s[mf][0][0], mt1 = s[mf][0][2];
            #pragma unroll
            for (int jn = 0; jn < 8; jn++) {
                mt0 = fmaxf(mt0, fmaxf(s[mf][jn][0], s[mf][jn][1]));
                mt1 = fmaxf(mt1, fmaxf(s[mf][jn][2], s[mf][jn][3]));
            }
            mt0 = fmaxf(mt0, __shfl_xor_sync(0xffffffffu, mt0, 1));
            mt0 = fmaxf(mt0, __shfl_xor_sync(0xffffffffu, mt0, 2));
            mt1 = fmaxf(mt1, __shfl_xor_sync(0xffffffffu, mt1, 1));
            mt1 = fmaxf(mt1, __shfl_xor_sync(0xffffffffu, mt1, 2));
            const float mn0 = fmaxf(m[mf][0], mt0), mn1 = fmaxf(m[mf][1], mt1);
            corr[mf][0] = fexp2(m[mf][0] - mn0);
            corr[mf][1] = fexp2(m[mf][1] - mn1);
            m[mf][0] = mn0; m[mf][1] = mn1;
            float ls0 = 0.f, ls1 = 0.f;
            #pragma unroll
            for (int jn = 0; jn < 8; jn++) {
                s[mf][jn][0] = fexp2(s[mf][jn][0] - mn0); ls0 += s[mf][jn][0];
                s[mf][jn][1] = fexp2(s[mf][jn][1] - mn0); ls0 += s[mf][jn][1];
                s[mf][jn][2] = fexp2(s[mf][jn][2] - mn1); ls1 += s[mf][jn][2];
                s[mf][jn][3] = fexp2(s[mf][jn][3] - mn1); ls1 += s[mf][jn][3];
            }
            l[mf][0] = l[mf][0]*corr[mf][0] + ls0;
            l[mf][1] = l[mf][1]*corr[mf][1] + ls1;
            #pragma unroll
            for (int j = 0; j < 4; j++) {
                O[mf][j][0] *= corr[mf][0]; O[mf][j][1] *= corr[mf][0];
                O[mf][j][2] *= corr[mf][1]; O[mf][j][3] *= corr[mf][1];
            }
        }

        #pragma unroll
        for (int ks = 0; ks < 4; ks++) {
            uint32_t pa[2][4];
            #pragma unroll
            for (int mf = 0; mf < 2; mf++) {
                pa[mf][0] = cvt2h(s[mf][2*ks  ][1], s[mf][2*ks  ][0]);
                pa[mf][1] = cvt2h(s[mf][2*ks  ][3], s[mf][2*ks  ][2]);
                pa[mf][2] = cvt2h(s[mf][2*ks+1][1], s[mf][2*ks+1][0]);
                pa[mf][3] = cvt2h(s[mf][2*ks+1][3], s[mf][2*ks+1][2]);
            }
            #pragma unroll
            for (int jn = 0; jn < 4; jn++) {
                const uint32_t* vr = &Vs[buf][(jn*8 + g)*VSTRU + ks*8];
                uint32_t b0 = vr[t];
                uint32_t b1 = vr[t + 4];
                mma_f16(O[0][jn], pa[0], b0, b1);
                mma_f16(O[1][jn], pa[1], b0, b1);
            }
        }
        __syncthreads();
    }

    #pragma unroll
    for (int mf = 0; mf < 2; mf++) {
        float l0 = l[mf][0], l1 = l[mf][1];
        l0 += __shfl_xor_sync(0xffffffffu, l0, 1);
        l0 += __shfl_xor_sync(0xffffffffu, l0, 2);
        l1 += __shfl_xor_sync(0xffffffffu, l1, 1);
        l1 += __shfl_xor_sync(0xffffffffu, l1, 2);
        const float inv0 = 1.0f / l0, inv1 = 1.0f / l1;
        const int r0 = q0 + wid*32 + mf*16 + g;
        float* o0 = g_x + (bSS + r0)*CC + h*DD;
        float* o1 = o0 + 8*CC;
        #pragma unroll
        for (int jn = 0; jn < 4; jn++) {
            float2 u0 = make_float2(O[mf][jn][0]*inv0, O[mf][jn][1]*inv0);
            float2 u1 = make_float2(O[mf][jn][2]*inv1, O[mf][jn][3]*inv1);
            *reinterpret_cast<float2*>(o0 + jn*8 + 2*t) = u0;
            *reinterpret_cast<float2*>(o1 + jn*8 + 2*t) = u1;
        }
    }
}

// ---------------- launcher ----------------
extern "C" void kernel_launch(void* const* d_in, const int* in_sizes, int n_in,
                              void* d_out, int out_size)
{
    (void)in_sizes; (void)n_in; (void)out_size;
    const float* q = (const float*)d_in[0];
    const float* k = (const float*)d_in[1];
    const float* v = (const float*)d_in[2];
    float* out = (float*)d_out;

    QKVArgs qa;
    qa.in[0] = q; qa.in[1] = k; qa.in[2] = v;
    qa.ps[0] = ProjSet{ (const float*)d_in[3], (const float*)d_in[4],
                        (const float*)d_in[5], (const float*)d_in[6],
                        (const float*)d_in[7], (const float*)d_in[8] };
    qa.ps[1] = ProjSet{ (const float*)d_in[9], (const float*)d_in[10],
                        (const float*)d_in[11], (const float*)d_in[12],
                        (const float*)d_in[13], (const float*)d_in[14] };
    qa.ps[2] = ProjSet{ (const float*)d_in[15], (const float*)d_in[16],
                        (const float*)d_in[17], (const float*)d_in[18],
                        (const float*)d_in[19], (const float*)d_in[20] };

    MlpArgs ma;
    ma.w1a = (const float*)d_in[21]; ma.b1a = (const float*)d_in[22];
    ma.w2a = (const float*)d_in[23]; ma.b2a = (const float*)d_in[24];
    ma.w1b = (const float*)d_in[25]; ma.b1b = (const float*)d_in[26];
    ma.w2b = (const float*)d_in[27]; ma.b2b = (const float*)d_in[28];

    cudaFuncSetAttribute(qkv_proj_kernel,
                         cudaFuncAttributeMaxDynamicSharedMemorySize, PROJ_SMEM_BYTES);
    cudaFuncSetAttribute(mlp_fused_kernel,
                         cudaFuncAttributeMaxDynamicSharedMemorySize, MLP_SMEM_BYTES);

    // fused q/k/v projections -> g_qph/g_kph/(g_vp + g_vph)
    qkv_proj_kernel<<<384, 256, PROJ_SMEM_BYTES>>>(qa);

    // fp16 flash attention -> g_x
    attn_mma_kernel<<<dim3(SS/128, NH, BB), 128>>>();

    // fused rs1+rs2 -> out (CHW)
    mlp_fused_kernel<<<128, 256, MLP_SMEM_BYTES>>>(ma, out);
}

// round 11
// speedup vs baseline: 1.7550x; 1.1535x over previous
#include <cuda_runtime.h>
#include <math.h>
#include <stdint.h>

#define BB 2
#define CC 128
#define HH 256      // 2*C
#define SS 4096     // 64*64 tokens
#define NH 4
#define DD 32       // head dim

#define QS 0.1767766952966369f   // 1/sqrt(32)
#define QS2 (QS * 1.4426950408889634f)   // fold log2(e) for ex2-domain softmax

// ---------------- scratch (no allocation allowed) ----------------
__device__ uint32_t g_qph[BB*SS*CC/2];   // fp16 Q, token-major, pre-scaled by QS*log2e
__device__ uint32_t g_kph[BB*SS*CC/2];   // fp16 K, token-major
__device__ uint32_t g_vph[BB*SS*CC/2];   // fp16 V, d-major: [b][h][d][s]
__device__ float g_vp[BB*SS*CC];         // fp32 V (residual for mlp1)
__device__ float g_x [BB*SS*CC];         // attention output

// fp16 mma m16n8k16 row.col, fp32 accumulate
__device__ __forceinline__ void mma_f16(float* c, const uint32_t* a, uint32_t b0, uint32_t b1) {
    asm volatile(
        "mma.sync.aligned.m16n8k16.row.col.f32.f16.f16.f32 "
        "{%0,%1,%2,%3}, {%4,%5,%6,%7}, {%8,%9}, {%0,%1,%2,%3};"
        : "+f"(c[0]), "+f"(c[1]), "+f"(c[2]), "+f"(c[3])
        : "r"(a[0]), "r"(a[1]), "r"(a[2]), "r"(a[3]), "r"(b0), "r"(b1));
}
__device__ __forceinline__ float fexp2(float x) {
    float r;
    asm("ex2.approx.f32 %0, %1;" : "=f"(r) : "f"(x));
    return r;
}
// pack {hi, lo} floats -> f16x2 (lo in low half)
__device__ __forceinline__ uint32_t cvt2h(float hi, float lo) {
    uint32_t r;
    asm("cvt.rn.f16x2.f32 %0, %1, %2;" : "=r"(r) : "f"(hi), "f"(lo));
    return r;
}
__device__ __forceinline__ float leaky(float v) { return (v > 0.f) ? v : 0.01f*v; }

// ================= fp16 projection layouts (u32 units) =================
#define XSTRU 68    // X/H-row pairs: 64 pairs + pad4 (bank 4g+t)
#define HSTRU 36    // H chunk: 32 pairs + pad4
#define W1STRU 68   // W1h [n=64][kpair=64]+pad
#define W2STRU 36   // W2h [n=128][kpair=32]+pad
#define FSTR 132    // fp32 staging stride

// qkv smem (u32): Xh 4352 | Hch 2304 | W1h 4352 | W2h 4608 | Bs1 256 | Bs2 128 | Gs 128 | Bts 128 | MU 64 | RI 64
#define QKV_SMEM_U32 (4352 + 2304 + 4352 + 4608 + 256 + 128 + 128 + 128 + 64 + 64)
#define QKV_SMEM_BYTES (QKV_SMEM_U32*4)
// mlp smem (u32): Xh 4352 | Hch 2304 | W1h 4352 | W2h 4608 | Rs1f 8448 | Bs1 256 | Bs2 128
#define MLP_SMEM_U32 (4352 + 2304 + 4352 + 4608 + 8448 + 256 + 128)
#define MLP_SMEM_BYTES (MLP_SMEM_U32*4)

struct ProjSet { const float *gam, *bet, *w1, *b1, *w2, *b2; };
struct QKVArgs { const float* in[3]; ProjSet ps[3]; };
struct MlpArgs { const float *w1a, *b1a, *w2a, *b2a, *w1b, *b1b, *w2b, *b2b; };

// ================= fused q/k/v projection (fp16 GEMMs, 2 CTA/SM) =================
__global__ __launch_bounds__(256, 2)
void qkv_proj_kernel(QKVArgs a)
{
    extern __shared__ uint32_t smu[];
    uint32_t* Xh  = smu;                      // [64][68]
    uint32_t* Hch = Xh + 64*XSTRU;            // [64][36]
    uint32_t* W1h = Hch + 64*HSTRU;           // [64][68]
    uint32_t* W2h = W1h + 64*W1STRU;          // [128][36]
    float* Fst = (float*)W1h;                 // fp32 staging [64][132] (aliases W1h+W2h)
    float* Bs1 = (float*)(W2h + 128*W2STRU);
    float* Bs2 = Bs1 + 256;
    float* Gs  = Bs2 + 128;
    float* Bts = Gs + 128;
    float* MUs = Bts + 128;
    float* RIs = MUs + 64;

    const int grp = blockIdx.x >> 7;
    const int bx  = blockIdx.x & 127;
    const ProjSet& p = a.ps[grp];
    const float* in = a.in[grp];
    const float* w1 = p.w1;
    const float* w2 = p.w2;

    const int tid  = threadIdx.x;
    const int wid  = tid >> 5;
    const int lane = tid & 31;
    const int g    = lane >> 2;
    const int t    = lane & 3;
    const int mrow  = (wid & 3) * 16;
    const int nhalf = (wid >> 2) * 32;

    const int gt0 = bx * 64;
    const int b   = gt0 >> 12;
    const int s0  = gt0 & (SS - 1);

    if (tid < 256) Bs1[tid] = p.b1[tid];
    if (tid < 128) { Bs2[tid] = p.b2[tid]; Gs[tid] = p.gam[tid]; Bts[tid] = p.bet[tid]; }

    // ---- load X (CHW) -> Fst fp32 ----
    {
        const float* base = in + (size_t)b*CC*SS + s0;
        for (int i = tid; i < 64*CC; i += 256) {
            int c = i >> 6, tt = i & 63;
            Fst[tt*FSTR + c] = base[c*SS + tt];
        }
    }
    __syncthreads();

    // ---- LN stats: 4 threads/token, shuffle reduce ----
    {
        int token = tid >> 2, q = tid & 3;
        float s = 0.f, s2 = 0.f;
        const float* xr = &Fst[token*FSTR];
        #pragma unroll 8
        for (int i = 0; i < 32; i++) { float v = xr[q + 4*i]; s += v; s2 += v*v; }
        s  += __shfl_xor_sync(0xffffffffu, s, 1);
        s  += __shfl_xor_sync(0xffffffffu, s, 2);
        s2 += __shfl_xor_sync(0xffffffffu, s2, 1);
        s2 += __shfl_xor_sync(0xffffffffu, s2, 2);
        if (q == 0) {
            float mu = s * (1.0f/CC);
            float var = s2 * (1.0f/CC) - mu*mu;
            MUs[token] = mu;
            RIs[token] = rsqrtf(var + 1e-5f);
        }
    }
    __syncthreads();

    // ---- normalize -> Xh fp16 ----
    for (int idx = tid; idx < 64*64; idx += 256) {
        int token = idx >> 6, pr = idx & 63, c = pr*2;
        float mu = MUs[token], ri = RIs[token];
        float v0 = (Fst[token*FSTR + c]   - mu)*ri*Gs[c]   + Bts[c];
        float v1 = (Fst[token*FSTR + c+1] - mu)*ri*Gs[c+1] + Bts[c+1];
        Xh[token*XSTRU + pr] = cvt2h(v1, v0);
    }
    __syncthreads();   // Fst dead; weight buffers usable

    float acc2[2][4][4];
    #pragma unroll
    for (int n2 = 0; n2 < 2; n2++)
        #pragma unroll
        for (int jn = 0; jn < 4; jn++)
            acc2[n2][jn][0] = acc2[n2][jn][1] = acc2[n2][jn][2] = acc2[n2][jn][3] = 0.f;

    #pragma unroll 1
    for (int hc = 0; hc < 4; hc++) {
        // ---- W1 chunk transposed load: [128k][64n] -> W1h[n][kpair] ----
        #pragma unroll
        for (int j = 0; j < 4; j++) {
            int idx = tid + j*256;
            int n = idx & 63, kk4 = (idx >> 6)*4;
            uint32_t u[4];
            #pragma unroll
            for (int z = 0; z < 4; z++) {
                int kk = kk4 + z;
                float e = w1[(size_t)(2*kk)*HH + hc*64 + n];
                float o = w1[(size_t)(2*kk+1)*HH + hc*64 + n];
                u[z] = cvt2h(o, e);
            }
            *reinterpret_cast<uint4*>(&W1h[n*W1STRU + kk4]) = make_uint4(u[0],u[1],u[2],u[3]);
        }
        __syncthreads();

        // ---- stage 1: Hc = leaky(X @ W1c + b1c) ----
        float acc[4][4];
        #pragma unroll
        for (int jn = 0; jn < 4; jn++)
            acc[jn][0] = acc[jn][1] = acc[jn][2] = acc[jn][3] = 0.f;
        #pragma unroll
        for (int ks = 0; ks < 8; ks++) {
            uint32_t av[4];
            const uint32_t* x0 = &Xh[(mrow+g)*XSTRU + ks*8];
            const uint32_t* x1 = x0 + 8*XSTRU;
            av[0] = x0[t]; av[1] = x1[t]; av[2] = x0[t+4]; av[3] = x1[t+4];
            #pragma unroll
            for (int jn = 0; jn < 4; jn++) {
                const uint32_t* wr = &W1h[(nhalf + jn*8 + g)*W1STRU + ks*8];
                mma_f16(acc[jn], av, wr[t], wr[t+4]);
            }
        }
        #pragma unroll
        for (int jn = 0; jn < 4; jn++) {
            int col = nhalf + jn*8 + 2*t;
            float c0 = leaky(acc[jn][0] + Bs1[hc*64 + col]);
            float c1 = leaky(acc[jn][1] + Bs1[hc*64 + col + 1]);
            float c2 = leaky(acc[jn][2] + Bs1[hc*64 + col]);
            float c3 = leaky(acc[jn][3] + Bs1[hc*64 + col + 1]);
            Hch[(mrow+g)*HSTRU + (col>>1)]   = cvt2h(c1, c0);
            Hch[(mrow+g+8)*HSTRU + (col>>1)] = cvt2h(c3, c2);
        }
        __syncthreads();

        // ---- W2 chunk transposed load: [64k][128n] -> W2h[n][kpair] ----
        #pragma unroll
        for (int j = 0; j < 4; j++) {
            int idx = tid + j*256;
            int n = idx & 127, kk4 = (idx >> 7)*4;
            uint32_t u[4];
            #pragma unroll
            for (int z = 0; z < 4; z++) {
                int kk = kk4 + z;
                float e = w2[(size_t)(hc*64 + 2*kk)*CC + n];
                float o = w2[(size_t)(hc*64 + 2*kk+1)*CC + n];
                u[z] = cvt2h(o, e);
            }
            *reinterpret_cast<uint4*>(&W2h[n*W2STRU + kk4]) = make_uint4(u[0],u[1],u[2],u[3]);
        }
        __syncthreads();

        // ---- stage 2 partial ----
        #pragma unroll
        for (int ks = 0; ks < 4; ks++) {
            uint32_t av[4];
            const uint32_t* h0 = &Hch[(mrow+g)*HSTRU + ks*8];
            const uint32_t* h1 = h0 + 8*HSTRU;
            av[0] = h0[t]; av[1] = h1[t]; av[2] = h0[t+4]; av[3] = h1[t+4];
            #pragma unroll
            for (int n2 = 0; n2 < 2; n2++) {
                #pragma unroll
                for (int jn = 0; jn < 4; jn++) {
                    const uint32_t* wr = &W2h[(n2*64 + nhalf + jn*8 + g)*W2STRU + ks*8];
                    mma_f16(acc2[n2][jn], av, wr[t], wr[t+4]);
                }
            }
        }
        __syncthreads();
    }

    // ---- Y -> Fst fp32 ----
    #pragma unroll
    for (int n2 = 0; n2 < 2; n2++) {
        #pragma unroll
        for (int jn = 0; jn < 4; jn++) {
            int col = n2*64 + nhalf + jn*8 + 2*t;
            float* y0 = &Fst[(mrow+g)*FSTR + col];
            float* y1 = &Fst[(mrow+g+8)*FSTR + col];
            y0[0] = acc2[n2][jn][0] + Bs2[col];
            y0[1] = acc2[n2][jn][1] + Bs2[col+1];
            y1[0] = acc2[n2][jn][2] + Bs2[col];
            y1[1] = acc2[n2][jn][3] + Bs2[col+1];
        }
    }
    __syncthreads();

    // ---- grp-specific outputs ----
    if (grp < 2) {
        uint32_t* ob = (grp == 0 ? g_qph : g_kph) + (size_t)gt0*64;
        const float sc = (grp == 0) ? QS2 : 1.0f;
        for (int i = tid; i < 64*64; i += 256) {
            int tt = i >> 6, c2 = (i & 63)*2;
            float lo = Fst[tt*FSTR + c2] * sc;
            float hi = Fst[tt*FSTR + c2 + 1] * sc;
            ob[(size_t)tt*64 + (i & 63)] = cvt2h(hi, lo);
        }
    } else {
        float* ob = g_vp + (size_t)gt0*CC;
        for (int i = tid; i < 64*CC; i += 256) {
            int tt = i >> 7, c = i & 127;
            ob[i] = Fst[tt*FSTR + c];
        }
        for (int i = tid; i < 128*32; i += 256) {
            int c = i >> 5, tp = (i & 31)*2;
            float lo = Fst[tp*FSTR + c];
            float hi = Fst[(tp+1)*FSTR + c];
            size_t u32idx = ((size_t)(b*NH + (c >> 5))*DD + (c & 31))*(SS/2) + (s0 + tp)/2;
            g_vph[u32idx] = cvt2h(hi, lo);
        }
    }
}

// ================= fused MLP1+MLP2 (fp16 GEMMs, register-prefetched weights) =================
__global__ __launch_bounds__(256, 1)
void mlp_fused_kernel(MlpArgs ag, float* __restrict__ out)
{
    extern __shared__ uint32_t smu[];
    uint32_t* Xh   = smu;                     // [64][68]
    uint32_t* Hch  = Xh + 64*XSTRU;           // [64][36]
    uint32_t* W1h  = Hch + 64*HSTRU;          // [64][68]
    uint32_t* W2h  = W1h + 64*W1STRU;         // [128][36]
    float* Rs1f = (float*)(W2h + 128*W2STRU); // [64][132] fp32
    float* Bs1  = Rs1f + 64*FSTR;
    float* Bs2  = Bs1 + 256;

    const int tid  = threadIdx.x;
    const int wid  = tid >> 5;
    const int lane = tid & 31;
    const int g    = lane >> 2;
    const int t    = lane & 3;
    const int mrow  = (wid & 3) * 16;
    const int nhalf = (wid >> 2) * 32;

    const int gt0 = blockIdx.x * 64;
    const int b   = gt0 >> 12;
    const int s0  = gt0 & (SS - 1);

    const int wn1  = tid & 63,  wk1 = ((tid >> 6) & 3)*4;   // base W1 coords (j adds via idx)
    (void)wn1; (void)wk1;

    float wreg[32];
    // prefetch m1_w1 chunk 0 (strided fp32)
    #pragma unroll
    for (int j = 0; j < 4; j++) {
        int idx = tid + j*256;
        int n = idx & 63, kk4 = (idx >> 6)*4;
        #pragma unroll
        for (int z = 0; z < 4; z++) {
            int kk = kk4 + z;
            wreg[j*8 + z*2 + 0] = ag.w1a[(size_t)(2*kk)*HH + n];
            wreg[j*8 + z*2 + 1] = ag.w1a[(size_t)(2*kk+1)*HH + n];
        }
    }

    // load X (attention output) -> Xh fp16
    {
        const float* base = g_x + (size_t)gt0*CC;
        for (int idx = tid; idx < 64*64; idx += 256) {
            int token = idx >> 6, pr = idx & 63;
            float2 v = *reinterpret_cast<const float2*>(&base[token*CC + 2*pr]);
            Xh[token*XSTRU + pr] = cvt2h(v.y, v.x);
        }
    }

    #pragma unroll 1
    for (int mm = 0; mm < 2; mm++) {
        const float* w1 = mm ? ag.w1b : ag.w1a;
        const float* b1 = mm ? ag.b1b : ag.b1a;
        const float* w2 = mm ? ag.w2b : ag.w2a;
        const float* b2 = mm ? ag.b2b : ag.b2a;
        const float* w1_next = mm ? nullptr : ag.w1b;

        if (tid < 256) Bs1[tid] = b1[tid];
        if (tid < 128) Bs2[tid] = b2[tid];

        float acc2[2][4][4];
        #pragma unroll
        for (int n2 = 0; n2 < 2; n2++)
            #pragma unroll
            for (int jn = 0; jn < 4; jn++)
                acc2[n2][jn][0] = acc2[n2][jn][1] = acc2[n2][jn][2] = acc2[n2][jn][3] = 0.f;

        #pragma unroll 1
        for (int hc = 0; hc < 4; hc++) {
            // store W1 regs -> W1h (transpose/cvt), prefetch W2 chunk hc
            #pragma unroll
            for (int j = 0; j < 4; j++) {
                int idx = tid + j*256;
                int n = idx & 63, kk4 = (idx >> 6)*4;
                uint32_t u[4];
                #pragma unroll
                for (int z = 0; z < 4; z++)
                    u[z] = cvt2h(wreg[j*8 + z*2 + 1], wreg[j*8 + z*2]);
                *reinterpret_cast<uint4*>(&W1h[n*W1STRU + kk4]) = make_uint4(u[0],u[1],u[2],u[3]);
            }
            #pragma unroll
            for (int j = 0; j < 4; j++) {
                int idx = tid + j*256;
                int n = idx & 127, kk4 = (idx >> 7)*4;
                #pragma unroll
                for (int z = 0; z < 4; z++) {
                    int kk = kk4 + z;
                    wreg[j*8 + z*2 + 0] = w2[(size_t)(hc*64 + 2*kk)*CC + n];
                    wreg[j*8 + z*2 + 1] = w2[(size_t)(hc*64 + 2*kk+1)*CC + n];
                }
            }
            __syncthreads();

            // stage 1
            float acc[4][4];
            #pragma unroll
            for (int jn = 0; jn < 4; jn++)
                acc[jn][0] = acc[jn][1] = acc[jn][2] = acc[jn][3] = 0.f;
            #pragma unroll
            for (int ks = 0; ks < 8; ks++) {
                uint32_t av[4];
                const uint32_t* x0 = &Xh[(mrow+g)*XSTRU + ks*8];
                const uint32_t* x1 = x0 + 8*XSTRU;
                av[0] = x0[t]; av[1] = x1[t]; av[2] = x0[t+4]; av[3] = x1[t+4];
                #pragma unroll
                for (int jn = 0; jn < 4; jn++) {
                    const uint32_t* wr = &W1h[(nhalf + jn*8 + g)*W1STRU + ks*8];
                    mma_f16(acc[jn], av, wr[t], wr[t+4]);
                }
            }
            #pragma unroll
            for (int jn = 0; jn < 4; jn++) {
                int col = nhalf + jn*8 + 2*t;
                float c0 = leaky(acc[jn][0] + Bs1[hc*64 + col]);
                float c1 = leaky(acc[jn][1] + Bs1[hc*64 + col + 1]);
                float c2 = leaky(acc[jn][2] + Bs1[hc*64 + col]);
                float c3 = leaky(acc[jn][3] + Bs1[hc*64 + col + 1]);
                Hch[(mrow+g)*HSTRU + (col>>1)]   = cvt2h(c1, c0);
                Hch[(mrow+g+8)*HSTRU + (col>>1)] = cvt2h(c3, c2);
            }
            __syncthreads();

            // store W2 regs -> W2h, prefetch next W1 chunk
            #pragma unroll
            for (int j = 0; j < 4; j++) {
                int idx = tid + j*256;
                int n = idx & 127, kk4 = (idx >> 7)*4;
                uint32_t u[4];
                #pragma unroll
                for (int z = 0; z < 4; z++)
                    u[z] = cvt2h(wreg[j*8 + z*2 + 1], wreg[j*8 + z*2]);
                *reinterpret_cast<uint4*>(&W2h[n*W2STRU + kk4]) = make_uint4(u[0],u[1],u[2],u[3]);
            }
            if (hc < 3) {
                #pragma unroll
                for (int j = 0; j < 4; j++) {
                    int idx = tid + j*256;
                    int n = idx & 63, kk4 = (idx >> 6)*4;
                    #pragma unroll
                    for (int z = 0; z < 4; z++) {
                        int kk = kk4 + z;
                        wreg[j*8 + z*2 + 0] = w1[(size_t)(2*kk)*HH + (hc+1)*64 + n];
                        wreg[j*8 + z*2 + 1] = w1[(size_t)(2*kk+1)*HH + (hc+1)*64 + n];
                    }
                }
            } else if (w1_next) {
                #pragma unroll
                for (int j = 0; j < 4; j++) {
                    int idx = tid + j*256;
                    int n = idx & 63, kk4 = (idx >> 6)*4;
                    #pragma unroll
                    for (int z = 0; z < 4; z++) {
                        int kk = kk4 + z;
                        wreg[j*8 + z*2 + 0] = w1_next[(size_t)(2*kk)*HH + n];
                        wreg[j*8 + z*2 + 1] = w1_next[(size_t)(2*kk+1)*HH + n];
                    }
                }
            }
            __syncthreads();

            // stage 2 partial
            #pragma unroll
            for (int ks = 0; ks < 4; ks++) {
                uint32_t av[4];
                const uint32_t* h0 = &Hch[(mrow+g)*HSTRU + ks*8];
                const uint32_t* h1 = h0 + 8*HSTRU;
                av[0] = h0[t]; av[1] = h1[t]; av[2] = h0[t+4]; av[3] = h1[t+4];
                #pragma unroll
                for (int n2 = 0; n2 < 2; n2++) {
                    #pragma unroll
                    for (int jn = 0; jn < 4; jn++) {
                        const uint32_t* wr = &W2h[(n2*64 + nhalf + jn*8 + g)*W2STRU + ks*8];
                        mma_f16(acc2[n2][jn], av, wr[t], wr[t+4]);
                    }
                }
            }
            __syncthreads();
        }

        if (mm == 0) {
            // rs1 = Y1 + b2 (fp32 -> Rs1f)
            #pragma unroll
            for (int n2 = 0; n2 < 2; n2++) {
                #pragma unroll
                for (int jn = 0; jn < 4; jn++) {
                    int col = n2*64 + nhalf + jn*8 + 2*t;
                    float* y0 = &Rs1f[(mrow+g)*FSTR + col];
                    float* y1 = &Rs1f[(mrow+g+8)*FSTR + col];
                    y0[0] = acc2[n2][jn][0] + Bs2[col];
                    y0[1] = acc2[n2][jn][1] + Bs2[col+1];
                    y1[0] = acc2[n2][jn][2] + Bs2[col];
                    y1[1] = acc2[n2][jn][3] + Bs2[col+1];
                }
            }
            __syncthreads();
            // rs1 += vp; Xh = fp16(rs1)
            const float* rb = g_vp + (size_t)gt0*CC;
            for (int idx = tid; idx < 64*64; idx += 256) {
                int token = idx >> 6, pr = idx & 63;
                float2 vv = *reinterpret_cast<const float2*>(&rb[token*CC + 2*pr]);
                float r0 = Rs1f[token*FSTR + 2*pr]     + vv.x;
                float r1 = Rs1f[token*FSTR + 2*pr + 1] + vv.y;
                Rs1f[token*FSTR + 2*pr]     = r0;
                Rs1f[token*FSTR + 2*pr + 1] = r1;
                Xh[token*XSTRU + pr] = cvt2h(r1, r0);
            }
            __syncthreads();
        } else {
            // rs2 = rs1 + Y2 + b2 -> CHW out
            #pragma unroll
            for (int n2 = 0; n2 < 2; n2++) {
                #pragma unroll
                for (int jn = 0; jn < 4; jn++) {
                    int col = n2*64 + nhalf + jn*8 + 2*t;
                    float* y0 = &Rs1f[(mrow+g)*FSTR + col];
                    float* y1 = &Rs1f[(mrow+g+8)*FSTR + col];
                    y0[0] += acc2[n2][jn][0] + Bs2[col];
                    y0[1] += acc2[n2][jn][1] + Bs2[col+1];
                    y1[0] += acc2[n2][jn][2] + Bs2[col];
                    y1[1] += acc2[n2][jn][3] + Bs2[col+1];
                }
            }
            __syncthreads();
            float* ob = out + (size_t)b*CC*SS + s0;
            for (int i = tid; i < 64*CC; i += 256) {
                int c = i >> 6, tt = i & 63;
                ob[c*SS + tt] = Rs1f[tt*FSTR + c];
            }
        }
    }
}

// ================= fp16 mma.sync flash attention (unchanged, known-good) =================
#define KSTRU 20
#define VSTRU 36

__global__ __launch_bounds__(128, 2) void attn_mma_kernel()
{
    __shared__ uint32_t Ks[2][64*KSTRU];
    __shared__ uint32_t Vs[2][32*VSTRU];

    const int tid  = threadIdx.x;
    const int wid  = tid >> 5;
    const int lane = tid & 31;
    const int g    = lane >> 2;
    const int t    = lane & 3;
    const int h = blockIdx.y, b = blockIdx.z;
    const int q0 = blockIdx.x * 128;

    const size_t bSS = (size_t)b*SS;
    const uint32_t* kph = g_kph + bSS*64 + h*16;
    const uint32_t* vph = g_vph + ((size_t)(b*NH + h)*DD)*(SS/2);

    uint32_t qa[2][2][4];
    #pragma unroll
    for (int mf = 0; mf < 2; mf++) {
        const int r0 = q0 + wid*32 + mf*16 + g;
        const uint32_t* q0r = g_qph + (bSS + r0)*64 + h*16;
        const uint32_t* q1r = q0r + 8*64;
        #pragma unroll
        for (int ks = 0; ks < 2; ks++) {
            qa[mf][ks][0] = q0r[ks*8 + t];
            qa[mf][ks][1] = q1r[ks*8 + t];
            qa[mf][ks][2] = q0r[ks*8 + t + 4];
            qa[mf][ks][3] = q1r[ks*8 + t + 4];
        }
    }

    float O[2][4][4];
    float m[2][2], l[2][2];
    #pragma unroll
    for (int mf = 0; mf < 2; mf++) {
        #pragma unroll
        for (int j = 0; j < 4; j++)
            #pragma unroll
            for (int i = 0; i < 4; i++) O[mf][j][i] = 0.f;
        m[mf][0] = m[mf][1] = -1e30f;
        l[mf][0] = l[mf][1] = 0.f;
    }

    auto cp_tile = [&](int tile, int buf) {
        #pragma unroll
        for (int r = 0; r < 2; r++) {
            int idx = tid + r*128;
            {
                int row = idx >> 2, ch = idx & 3;
                const uint32_t* src = kph + (size_t)(tile*64 + row)*64 + ch*4;
                uint32_t d = (uint32_t)__cvta_generic_to_shared(&Ks[buf][row*KSTRU + ch*4]);
                asm volatile("cp.async.ca.shared.global [%0], [%1], 16;" :: "r"(d), "l"(src));
            }
            {
                int dd = idx >> 3, ch = idx & 7;
                const uint32_t* src = vph + (size_t)dd*(SS/2) + tile*32 + ch*4;
                uint32_t d = (uint32_t)__cvta_generic_to_shared(&Vs[buf][dd*VSTRU + ch*4]);
                asm volatile("cp.async.ca.shared.global [%0], [%1], 16;" :: "r"(d), "l"(src));
            }
        }
        asm volatile("cp.async.commit_group;" ::: "memory");
    };

    cp_tile(0, 0);

    for (int tile = 0; tile < SS/64; tile++) {
        const int buf = tile & 1;
        if (tile + 1 < SS/64) {
            cp_tile(tile + 1, buf ^ 1);
            asm volatile("cp.async.wait_group 1;" ::: "memory");
        } else {
            asm volatile("cp.async.wait_group 0;" ::: "memory");
        }
        __syncthreads();

        float s[2][8][4];
        #pragma unroll
        for (int jn = 0; jn < 8; jn++) {
            #pragma unroll
            for (int mf = 0; mf < 2; mf++)
                s[mf][jn][0] = s[mf][jn][1] = s[mf][jn][2] = s[mf][jn][3] = 0.f;
            const uint32_t* kr = &Ks[buf][(jn*8 + g)*KSTRU];
            #pragma unroll
            for (int ks = 0; ks < 2; ks++) {
                uint32_t b0 = kr[ks*8 + t];
                uint32_t b1 = kr[ks*8 + t + 4];
                mma_f16(s[0][jn], qa[0][ks], b0, b1);
                mma_f16(s[1][jn], qa[1][ks], b0, b1);
            }
        }

        float corr[2][2];
        #pragma unroll
        for (int mf = 0; mf < 2; mf++) {
            float mt0 = s[mf][0][0], mt1 = s[mf][0][2];
            #pragma unroll
            for (int jn = 0; jn < 8; jn++) {
                mt0 = fmaxf(mt0, fmaxf(s[mf][jn][0], s[mf][jn][1]));
                mt1 = fmaxf(mt1, fmaxf(s[mf][jn][2], s[mf][jn][3]));
            }
            mt0 = fmaxf(mt0, __shfl_xor_sync(0xffffffffu, mt0, 1));
            mt0 = fmaxf(mt0, __shfl_xor_sync(0xffffffffu, mt0, 2));
            mt1 = fmaxf(mt1, __shfl_xor_sync(0xffffffffu, mt1, 1));
            mt1 = fmaxf(mt1, __shfl_xor_sync(0xffffffffu, mt1, 2));
            const float mn0 = fmaxf(m[mf][0], mt0), mn1 = fmaxf(m[mf][1], mt1);
            corr[mf][0] = fexp2(m[mf][0] - mn0);
            corr[mf][1] = fexp2(m[mf][1] - mn1);
            m[mf][0] = mn0; m[mf][1] = mn1;
            float ls0 = 0.f, ls1 = 0.f;
            #pragma unroll
            for (int jn = 0; jn < 8; jn++) {
                s[mf][jn][0] = fexp2(s[mf][jn][0] - mn0); ls0 += s[mf][jn][0];
                s[mf][jn][1] = fexp2(s[mf][jn][1] - mn0); ls0 += s[mf][jn][1];
                s[mf][jn][2] = fexp2(s[mf][jn][2] - mn1); ls1 += s[mf][jn][2];
                s[mf][jn][3] = fexp2(s[mf][jn][3] - mn1); ls1 += s[mf][jn][3];
            }
            l[mf][0] = l[mf][0]*corr[mf][0] + ls0;
            l[mf][1] = l[mf][1]*corr[mf][1] + ls1;
            #pragma unroll
            for (int j = 0; j < 4; j++) {
                O[mf][j][0] *= corr[mf][0]; O[mf][j][1] *= corr[mf][0];
                O[mf][j][2] *= corr[mf][1]; O[mf][j][3] *= corr[mf][1];
            }
        }

        #pragma unroll
        for (int ks = 0; ks < 4; ks++) {
            uint32_t pa[2][4];
            #pragma unroll
            for (int mf = 0; mf < 2; mf++) {
                pa[mf][0] = cvt2h(s[mf][2*ks  ][1], s[mf][2*ks  ][0]);
                pa[mf][1] = cvt2h(s[mf][2*ks  ][3], s[mf][2*ks  ][2]);
                pa[mf][2] = cvt2h(s[mf][2*ks+1][1], s[mf][2*ks+1][0]);
                pa[mf][3] = cvt2h(s[mf][2*ks+1][3], s[mf][2*ks+1][2]);
            }
            #pragma unroll
            for (int jn = 0; jn < 4; jn++) {
                const uint32_t* vr = &Vs[buf][(jn*8 + g)*VSTRU + ks*8];
                uint32_t b0 = vr[t];
                uint32_t b1 = vr[t + 4];
                mma_f16(O[0][jn], pa[0], b0, b1);
                mma_f16(O[1][jn], pa[1], b0, b1);
            }
        }
        __syncthreads();
    }

    #pragma unroll
    for (int mf = 0; mf < 2; mf++) {
        float l0 = l[mf][0], l1 = l[mf][1];
        l0 += __shfl_xor_sync(0xffffffffu, l0, 1);
        l0 += __shfl_xor_sync(0xffffffffu, l0, 2);
        l1 += __shfl_xor_sync(0xffffffffu, l1, 1);
        l1 += __shfl_xor_sync(0xffffffffu, l1, 2);
        const float inv0 = 1.0f / l0, inv1 = 1.0f / l1;
        const int r0 = q0 + wid*32 + mf*16 + g;
        float* o0 = g_x + (bSS + r0)*CC + h*DD;
        float* o1 = o0 + 8*CC;
        #pragma unroll
        for (int jn = 0; jn < 4; jn++) {
            float2 u0 = make_float2(O[mf][jn][0]*inv0, O[mf][jn][1]*inv0);
            float2 u1 = make_float2(O[mf][jn][2]*inv1, O[mf][jn][3]*inv1);
            *reinterpret_cast<float2*>(o0 + jn*8 + 2*t) = u0;
            *reinterpret_cast<float2*>(o1 + jn*8 + 2*t) = u1;
        }
    }
}

// ---------------- launcher ----------------
extern "C" void kernel_launch(void* const* d_in, const int* in_sizes, int n_in,
                              void* d_out, int out_size)
{
    (void)in_sizes; (void)n_in; (void)out_size;
    const float* q = (const float*)d_in[0];
    const float* k = (const float*)d_in[1];
    const float* v = (const float*)d_in[2];
    float* out = (float*)d_out;

    QKVArgs qa;
    qa.in[0] = q; qa.in[1] = k; qa.in[2] = v;
    qa.ps[0] = ProjSet{ (const float*)d_in[3], (const float*)d_in[4],
                        (const float*)d_in[5], (const float*)d_in[6],
                        (const float*)d_in[7], (const float*)d_in[8] };
    qa.ps[1] = ProjSet{ (const float*)d_in[9], (const float*)d_in[10],
                        (const float*)d_in[11], (const float*)d_in[12],
                        (const float*)d_in[13], (const float*)d_in[14] };
    qa.ps[2] = ProjSet{ (const float*)d_in[15], (const float*)d_in[16],
                        (const float*)d_in[17], (const float*)d_in[18],
                        (const float*)d_in[19], (const float*)d_in[20] };

    MlpArgs ma;
    ma.w1a = (const float*)d_in[21]; ma.b1a = (const float*)d_in[22];
    ma.w2a = (const float*)d_in[23]; ma.b2a = (const float*)d_in[24];
    ma.w1b = (const float*)d_in[25]; ma.b1b = (const float*)d_in[26];
    ma.w2b = (const float*)d_in[27]; ma.b2b = (const float*)d_in[28];

    cudaFuncSetAttribute(qkv_proj_kernel,
                         cudaFuncAttributeMaxDynamicSharedMemorySize, QKV_SMEM_BYTES);
    cudaFuncSetAttribute(mlp_fused_kernel,
                         cudaFuncAttributeMaxDynamicSharedMemorySize, MLP_SMEM_BYTES);

    // fused q/k/v projections -> g_qph/g_kph/(g_vp + g_vph)
    qkv_proj_kernel<<<384, 256, QKV_SMEM_BYTES>>>(qa);

    // fp16 flash attention -> g_x
    attn_mma_kernel<<<dim3(SS/128, NH, BB), 128>>>();

    // fused rs1+rs2 -> out (CHW)
    mlp_fused_kernel<<<128, 256, MLP_SMEM_BYTES>>>(ma, out);
}